// round 7
// baseline (speedup 1.0000x reference)
#include <cuda_runtime.h>
#include <cuda_fp16.h>
#include <math.h>

// Problem shape (fixed by dataset)
#define B_    2
#define N_    50000
#define D_    128
#define E_    800000
#define ROWS_ (B_ * N_)   // 100000 rows when H viewed as [B*N, D]

// Scratch: device globals (no allocation allowed)
// m stored fp16, node-interleaved: g_mh[node*256 + batch*128 + d]
__device__ __half g_mh[(size_t)N_ * 256];
__device__ int    g_idx_is64;               // 1 if src/dst are int64, else int32
__device__ int    g_count[N_];              // in-degree histogram
__device__ int    g_offset[N_ + 1];         // CSR offsets
__device__ int    g_cursor[N_];             // fill cursors
__device__ int    g_esrc[E_];               // edge src ids grouped by dst

// ---------------------------------------------------------------------------
// Kernel 0: detect index dtype (graph-safe, deterministic).
// ---------------------------------------------------------------------------
__global__ void detect_idx_kernel(const unsigned int* __restrict__ src_w,
                                  const unsigned int* __restrict__ dst_w) {
    if (threadIdx.x == 0 && blockIdx.x == 0) {
        unsigned int acc = 0;
#pragma unroll 8
        for (int i = 0; i < 64; i++) {
            acc |= src_w[2 * i + 1];
            acc |= dst_w[2 * i + 1];
        }
        g_idx_is64 = (acc == 0u) ? 1 : 0;
    }
}

// ---------------------------------------------------------------------------
// Kernel 1: zero the histogram
// ---------------------------------------------------------------------------
__global__ void zero_count_kernel() {
    int i = blockIdx.x * blockDim.x + threadIdx.x;
    if (i < N_) g_count[i] = 0;
}

// ---------------------------------------------------------------------------
// Kernel 2: in-degree histogram over dst (8 edges/thread, vector loads)
// ---------------------------------------------------------------------------
__global__ void hist_kernel(const void* __restrict__ dst) {
    int i = blockIdx.x * blockDim.x + threadIdx.x;
    if (i * 8 >= E_) return;
    int d[8];
    if (g_idx_is64) {
#pragma unroll
        for (int q = 0; q < 4; q++) {
            longlong2 a = ((const longlong2*)dst)[i * 4 + q];
            d[q * 2] = (int)a.x; d[q * 2 + 1] = (int)a.y;
        }
    } else {
#pragma unroll
        for (int q = 0; q < 2; q++) {
            int4 v = ((const int4*)dst)[i * 2 + q];
            d[q * 4] = v.x; d[q * 4 + 1] = v.y; d[q * 4 + 2] = v.z; d[q * 4 + 3] = v.w;
        }
    }
#pragma unroll
    for (int q = 0; q < 8; q++) atomicAdd(&g_count[d[q]], 1);
}

// ---------------------------------------------------------------------------
// Kernel 3: single-block exclusive scan over g_count -> g_offset, g_cursor
// ---------------------------------------------------------------------------
__global__ __launch_bounds__(1024)
void scan_kernel() {
    __shared__ int sh[1024];
    const int tid = threadIdx.x;
    const int per = (N_ + 1023) / 1024;  // 49
    const int base = tid * per;

    int s = 0;
    for (int i = 0; i < per; i++) {
        int j = base + i;
        if (j < N_) s += g_count[j];
    }
    sh[tid] = s;
    __syncthreads();

    for (int o = 1; o < 1024; o <<= 1) {
        int t = (tid >= o) ? sh[tid - o] : 0;
        __syncthreads();
        sh[tid] += t;
        __syncthreads();
    }
    int run = sh[tid] - s;  // exclusive prefix for this chunk

    for (int i = 0; i < per; i++) {
        int j = base + i;
        if (j < N_) {
            g_offset[j] = run;
            g_cursor[j] = run;
            run += g_count[j];
        }
    }
    if (tid == 1023) g_offset[N_] = E_;
}

// ---------------------------------------------------------------------------
// Kernel 4: bucket edges by dst (4 edges/thread):  g_esrc[cursor[d]++] = src[e]
// ---------------------------------------------------------------------------
__global__ void fill_kernel(const void* __restrict__ src,
                            const void* __restrict__ dst) {
    int i = blockIdx.x * blockDim.x + threadIdx.x;
    if (i * 4 >= E_) return;
    int s0, s1, s2, s3, d0, d1, d2, d3;
    if (g_idx_is64) {
        longlong2 sa = ((const longlong2*)src)[i * 2];
        longlong2 sb = ((const longlong2*)src)[i * 2 + 1];
        longlong2 da = ((const longlong2*)dst)[i * 2];
        longlong2 db = ((const longlong2*)dst)[i * 2 + 1];
        s0 = (int)sa.x; s1 = (int)sa.y; s2 = (int)sb.x; s3 = (int)sb.y;
        d0 = (int)da.x; d1 = (int)da.y; d2 = (int)db.x; d3 = (int)db.y;
    } else {
        int4 sv = ((const int4*)src)[i];
        int4 dv = ((const int4*)dst)[i];
        s0 = sv.x; s1 = sv.y; s2 = sv.z; s3 = sv.w;
        d0 = dv.x; d1 = dv.y; d2 = dv.z; d3 = dv.w;
    }
    g_esrc[atomicAdd(&g_cursor[d0], 1)] = s0;
    g_esrc[atomicAdd(&g_cursor[d1], 1)] = s1;
    g_esrc[atomicAdd(&g_cursor[d2], 1)] = s2;
    g_esrc[atomicAdd(&g_cursor[d3], 1)] = s3;
}

// ---------------------------------------------------------------------------
// Kernel 5: SGEMM  m[r,:] = H[r,:] @ W, packed f32x2 FMAs, fp16 output
// into node-interleaved layout. Block tile 128x128, 256 threads, 8x8/thread.
// ---------------------------------------------------------------------------
__device__ __forceinline__ unsigned long long pack2(float v) {
    unsigned long long r;
    unsigned int u = __float_as_uint(v);
    asm("mov.b64 %0, {%1, %1};" : "=l"(r) : "r"(u));
    return r;
}
#define FMA2(d, a, b, c) \
    asm("fma.rn.f32x2 %0, %1, %2, %3;" : "=l"(d) : "l"(a), "l"(b), "l"(c))

__global__ __launch_bounds__(256, 1)
void gemm_kernel(const float* __restrict__ Hm, const float* __restrict__ W) {
    extern __shared__ float sm[];
    float* As = sm;              // [128][128] (row, k)
    float* Bs = sm + 128 * 128;  // [128][128] (k, col)

    const int tid  = threadIdx.x;
    const int row0 = blockIdx.x * 128;

#pragma unroll
    for (int i = 0; i < 16; i++) {
        int fi = (i * 256 + tid) * 4;
        *(float4*)&Bs[fi] = *(const float4*)&W[fi];
    }
#pragma unroll
    for (int i = 0; i < 16; i++) {
        int idx4 = i * 256 + tid;
        int r = idx4 >> 5;
        int c = (idx4 & 31) * 4;
        float4 v = make_float4(0.f, 0.f, 0.f, 0.f);
        int gr = row0 + r;
        if (gr < ROWS_) v = *(const float4*)&Hm[(size_t)gr * D_ + c];
        *(float4*)&As[r * D_ + c] = v;
    }
    __syncthreads();

    const int tx = tid & 15;   // 16 col-groups of 8
    const int ty = tid >> 4;   // 16 row-groups of 8

    unsigned long long acc[8][4];
#pragma unroll
    for (int i = 0; i < 8; i++)
#pragma unroll
        for (int j = 0; j < 4; j++) acc[i][j] = 0ull;

#pragma unroll 4
    for (int k = 0; k < 128; k++) {
        unsigned long long bp[4];
        *(ulonglong2*)&bp[0] = *(ulonglong2*)&Bs[k * 128 + tx * 8];
        *(ulonglong2*)&bp[2] = *(ulonglong2*)&Bs[k * 128 + tx * 8 + 4];
        unsigned long long ap[8];
#pragma unroll
        for (int i = 0; i < 8; i++) ap[i] = pack2(As[(ty * 8 + i) * D_ + k]);
#pragma unroll
        for (int i = 0; i < 8; i++)
#pragma unroll
            for (int j = 0; j < 4; j++) FMA2(acc[i][j], ap[i], bp[j], acc[i][j]);
    }

#pragma unroll
    for (int i = 0; i < 8; i++) {
        int gr = row0 + ty * 8 + i;
        if (gr < ROWS_) {
            int b = (gr >= N_) ? 1 : 0;
            int n = gr - b * N_;
            __half2 h0 = __float22half2_rn(*(float2*)&acc[i][0]);
            __half2 h1 = __float22half2_rn(*(float2*)&acc[i][1]);
            __half2 h2 = __float22half2_rn(*(float2*)&acc[i][2]);
            __half2 h3 = __float22half2_rn(*(float2*)&acc[i][3]);
            uint4 v;
            v.x = *(unsigned int*)&h0;
            v.y = *(unsigned int*)&h1;
            v.z = *(unsigned int*)&h2;
            v.w = *(unsigned int*)&h3;
            *(uint4*)(g_mh + (size_t)n * 256 + b * 128 + tx * 8) = v;
        }
    }
}

// ---------------------------------------------------------------------------
// Kernel 6: fused gather-accumulate + gelu + residual + LayerNorm.
// One warp per dst node. Per edge: one contiguous 512B read (both batches).
// Inner loop batches 8 independent loads per lane to raise MLP (latency fix).
// Lanes 0-15 own batch 0 (8 features each), lanes 16-31 own batch 1.
// ---------------------------------------------------------------------------
__device__ __forceinline__ float gelu_exact(float v) {
    return 0.5f * v * (1.0f + erff(v * 0.70710678118654752f));
}

// reduce across the 16-lane half-group (xor offsets < 16 stay in-group)
__device__ __forceinline__ float half_sum(float s) {
#pragma unroll
    for (int o = 8; o > 0; o >>= 1) s += __shfl_xor_sync(0xffffffffu, s, o);
    return s;
}

#define ACC_V(v)                                            \
    do {                                                    \
        float2 f0 = __half22float2(*(__half2*)&(v).x);      \
        float2 f1 = __half22float2(*(__half2*)&(v).y);      \
        float2 f2 = __half22float2(*(__half2*)&(v).z);      \
        float2 f3 = __half22float2(*(__half2*)&(v).w);      \
        a0 += f0.x; a1 += f0.y; a2 += f1.x; a3 += f1.y;     \
        a4 += f2.x; a5 += f2.y; a6 += f3.x; a7 += f3.y;     \
    } while (0)

__global__ __launch_bounds__(256)
void gather_ln_kernel(const float* __restrict__ Hm,
                      const float* __restrict__ gamma,
                      const float* __restrict__ beta,
                      float* __restrict__ out) {
    const int node = (blockIdx.x * blockDim.x + threadIdx.x) >> 5;
    const int lane = threadIdx.x & 31;
    if (node >= N_) return;

    const int beg = g_offset[node];
    const int end = g_offset[node + 1];
    const size_t laneoff = (size_t)lane * 8;

    float a0 = 0.f, a1 = 0.f, a2 = 0.f, a3 = 0.f;
    float a4 = 0.f, a5 = 0.f, a6 = 0.f, a7 = 0.f;

    for (int base = beg; base < end; base += 32) {
        int k = base + lane;
        int myS = (k < end) ? g_esrc[k] : 0;
        int cnt = min(32, end - base);
        int j = 0;
        // 8-wide groups: 8 independent 16B loads per lane in flight
        for (; j + 8 <= cnt; j += 8) {
            uint4 v[8];
#pragma unroll
            for (int t = 0; t < 8; t++) {
                int s = __shfl_sync(0xffffffffu, myS, j + t);
                v[t] = *(const uint4*)(g_mh + (size_t)s * 256 + laneoff);
            }
#pragma unroll
            for (int t = 0; t < 8; t++) ACC_V(v[t]);
        }
        // 4-wide group
        if (j + 4 <= cnt) {
            uint4 v[4];
#pragma unroll
            for (int t = 0; t < 4; t++) {
                int s = __shfl_sync(0xffffffffu, myS, j + t);
                v[t] = *(const uint4*)(g_mh + (size_t)s * 256 + laneoff);
            }
#pragma unroll
            for (int t = 0; t < 4; t++) ACC_V(v[t]);
            j += 4;
        }
        // scalar tail
        for (; j < cnt; j++) {
            int s = __shfl_sync(0xffffffffu, myS, j);
            uint4 v = *(const uint4*)(g_mh + (size_t)s * 256 + laneoff);
            ACC_V(v);
        }
    }

    // lane -> (batch, feature group)
    const int bsel = lane >> 4;          // 0 or 1
    const int fg   = lane & 15;          // 16 groups of 8 features
    const size_t rowoff = (size_t)(bsel * N_ + node) * D_ + fg * 8;

    float4 h0 = *(const float4*)(Hm + rowoff);
    float4 h1 = *(const float4*)(Hm + rowoff + 4);

    float x0 = h0.x + gelu_exact(a0);
    float x1 = h0.y + gelu_exact(a1);
    float x2 = h0.z + gelu_exact(a2);
    float x3 = h0.w + gelu_exact(a3);
    float x4 = h1.x + gelu_exact(a4);
    float x5 = h1.y + gelu_exact(a5);
    float x6 = h1.z + gelu_exact(a6);
    float x7 = h1.w + gelu_exact(a7);

    float mean = half_sum(x0 + x1 + x2 + x3 + x4 + x5 + x6 + x7) * (1.0f / D_);

    float d0 = x0 - mean, d1 = x1 - mean, d2 = x2 - mean, d3 = x3 - mean;
    float d4 = x4 - mean, d5 = x5 - mean, d6 = x6 - mean, d7 = x7 - mean;
    float var = half_sum(d0 * d0 + d1 * d1 + d2 * d2 + d3 * d3 +
                         d4 * d4 + d5 * d5 + d6 * d6 + d7 * d7) * (1.0f / D_);
    float inv = rsqrtf(var + 1e-5f);

    float4 g0 = *(const float4*)(gamma + fg * 8);
    float4 g1 = *(const float4*)(gamma + fg * 8 + 4);
    float4 b0 = *(const float4*)(beta + fg * 8);
    float4 b1 = *(const float4*)(beta + fg * 8 + 4);

    float4 o0, o1;
    o0.x = d0 * inv * g0.x + b0.x;
    o0.y = d1 * inv * g0.y + b0.y;
    o0.z = d2 * inv * g0.z + b0.z;
    o0.w = d3 * inv * g0.w + b0.w;
    o1.x = d4 * inv * g1.x + b1.x;
    o1.y = d5 * inv * g1.y + b1.y;
    o1.z = d6 * inv * g1.z + b1.z;
    o1.w = d7 * inv * g1.w + b1.w;
    *(float4*)(out + rowoff)     = o0;
    *(float4*)(out + rowoff + 4) = o1;
}

// ---------------------------------------------------------------------------
// Launcher
// ---------------------------------------------------------------------------
extern "C" void kernel_launch(void* const* d_in, const int* in_sizes, int n_in,
                              void* d_out, int out_size) {
    const float* H     = (const float*)d_in[0];
    const void*  src   = d_in[1];
    const void*  dst   = d_in[2];
    const float* W     = (const float*)d_in[3];
    const float* gamma = (const float*)d_in[4];
    const float* beta  = (const float*)d_in[5];
    float*       out   = (float*)d_out;

    (void)in_sizes; (void)n_in; (void)out_size;

    cudaFuncSetAttribute(gemm_kernel,
                         cudaFuncAttributeMaxDynamicSharedMemorySize,
                         128 * 1024);

    // 0) index dtype probe
    detect_idx_kernel<<<1, 32>>>((const unsigned int*)src,
                                 (const unsigned int*)dst);
    // 1) CSR build (vectorized)
    zero_count_kernel<<<(N_ + 255) / 256, 256>>>();
    gemm_kernel<<<(ROWS_ + 127) / 128, 256, 128 * 1024>>>(H, W);
    hist_kernel<<<(E_ / 8 + 255) / 256, 256>>>(dst);
    scan_kernel<<<1, 1024>>>();
    fill_kernel<<<(E_ / 4 + 255) / 256, 256>>>(src, dst);
    // 2) fused gather + gelu + residual + LayerNorm (MLP-batched inner loop)
    gather_ln_kernel<<<(N_ * 32 + 255) / 256, 256>>>(H, gamma, beta, out);
}

// round 8
// speedup vs baseline: 1.0841x; 1.0841x over previous
#include <cuda_runtime.h>
#include <cuda_fp16.h>
#include <math.h>

// Problem shape (fixed by dataset)
#define B_    2
#define N_    50000
#define D_    128
#define E_    800000
#define ROWS_ (B_ * N_)   // 100000 rows when H viewed as [B*N, D]

// Scratch: device globals (no allocation allowed)
// m stored fp16, node-interleaved: g_mh[node*256 + batch*128 + d]
__device__ __half g_mh[(size_t)N_ * 256];
__device__ int    g_idx_is64;               // 1 if src/dst are int64, else int32
__device__ int    g_count[N_];              // in-degree histogram
__device__ int    g_offset[N_ + 1];         // CSR offsets
__device__ int    g_cursor[N_];             // fill cursors
__device__ int    g_esrc[E_];               // edge src ids grouped by dst

// ---------------------------------------------------------------------------
// Kernel 0: detect index dtype (graph-safe, deterministic).
// ---------------------------------------------------------------------------
__global__ void detect_idx_kernel(const unsigned int* __restrict__ src_w,
                                  const unsigned int* __restrict__ dst_w) {
    if (threadIdx.x == 0 && blockIdx.x == 0) {
        unsigned int acc = 0;
#pragma unroll 8
        for (int i = 0; i < 64; i++) {
            acc |= src_w[2 * i + 1];
            acc |= dst_w[2 * i + 1];
        }
        g_idx_is64 = (acc == 0u) ? 1 : 0;
    }
}

// ---------------------------------------------------------------------------
// Kernel 1: zero the histogram
// ---------------------------------------------------------------------------
__global__ void zero_count_kernel() {
    int i = blockIdx.x * blockDim.x + threadIdx.x;
    if (i < N_) g_count[i] = 0;
}

// ---------------------------------------------------------------------------
// Kernel 2: in-degree histogram over dst (4 edges/thread, vector loads)
// ---------------------------------------------------------------------------
__global__ void hist_kernel(const void* __restrict__ dst) {
    int i = blockIdx.x * blockDim.x + threadIdx.x;
    if (i * 4 >= E_) return;
    int d0, d1, d2, d3;
    if (g_idx_is64) {
        longlong2 a = ((const longlong2*)dst)[i * 2];
        longlong2 b = ((const longlong2*)dst)[i * 2 + 1];
        d0 = (int)a.x; d1 = (int)a.y; d2 = (int)b.x; d3 = (int)b.y;
    } else {
        int4 v = ((const int4*)dst)[i];
        d0 = v.x; d1 = v.y; d2 = v.z; d3 = v.w;
    }
    atomicAdd(&g_count[d0], 1);
    atomicAdd(&g_count[d1], 1);
    atomicAdd(&g_count[d2], 1);
    atomicAdd(&g_count[d3], 1);
}

// ---------------------------------------------------------------------------
// Kernel 3: single-block exclusive scan over g_count -> g_offset, g_cursor
// ---------------------------------------------------------------------------
__global__ __launch_bounds__(1024)
void scan_kernel() {
    __shared__ int sh[1024];
    const int tid = threadIdx.x;
    const int per = (N_ + 1023) / 1024;  // 49
    const int base = tid * per;

    int s = 0;
    for (int i = 0; i < per; i++) {
        int j = base + i;
        if (j < N_) s += g_count[j];
    }
    sh[tid] = s;
    __syncthreads();

    for (int o = 1; o < 1024; o <<= 1) {
        int t = (tid >= o) ? sh[tid - o] : 0;
        __syncthreads();
        sh[tid] += t;
        __syncthreads();
    }
    int run = sh[tid] - s;  // exclusive prefix for this chunk

    for (int i = 0; i < per; i++) {
        int j = base + i;
        if (j < N_) {
            g_offset[j] = run;
            g_cursor[j] = run;
            run += g_count[j];
        }
    }
    if (tid == 1023) g_offset[N_] = E_;
}

// ---------------------------------------------------------------------------
// Kernel 4: bucket edges by dst (4 edges/thread):  g_esrc[cursor[d]++] = src[e]
// ---------------------------------------------------------------------------
__global__ void fill_kernel(const void* __restrict__ src,
                            const void* __restrict__ dst) {
    int i = blockIdx.x * blockDim.x + threadIdx.x;
    if (i * 4 >= E_) return;
    int s0, s1, s2, s3, d0, d1, d2, d3;
    if (g_idx_is64) {
        longlong2 sa = ((const longlong2*)src)[i * 2];
        longlong2 sb = ((const longlong2*)src)[i * 2 + 1];
        longlong2 da = ((const longlong2*)dst)[i * 2];
        longlong2 db = ((const longlong2*)dst)[i * 2 + 1];
        s0 = (int)sa.x; s1 = (int)sa.y; s2 = (int)sb.x; s3 = (int)sb.y;
        d0 = (int)da.x; d1 = (int)da.y; d2 = (int)db.x; d3 = (int)db.y;
    } else {
        int4 sv = ((const int4*)src)[i];
        int4 dv = ((const int4*)dst)[i];
        s0 = sv.x; s1 = sv.y; s2 = sv.z; s3 = sv.w;
        d0 = dv.x; d1 = dv.y; d2 = dv.z; d3 = dv.w;
    }
    g_esrc[atomicAdd(&g_cursor[d0], 1)] = s0;
    g_esrc[atomicAdd(&g_cursor[d1], 1)] = s1;
    g_esrc[atomicAdd(&g_cursor[d2], 1)] = s2;
    g_esrc[atomicAdd(&g_cursor[d3], 1)] = s3;
}

// ---------------------------------------------------------------------------
// Kernel 5: SGEMM  m[r,:] = H[r,:] @ W, packed f32x2 FMAs, fp16 output
// into node-interleaved layout. Block tile 128x128, 256 threads, 8x8/thread.
// ---------------------------------------------------------------------------
__device__ __forceinline__ unsigned long long pack2(float v) {
    unsigned long long r;
    unsigned int u = __float_as_uint(v);
    asm("mov.b64 %0, {%1, %1};" : "=l"(r) : "r"(u));
    return r;
}
#define FMA2(d, a, b, c) \
    asm("fma.rn.f32x2 %0, %1, %2, %3;" : "=l"(d) : "l"(a), "l"(b), "l"(c))

__global__ __launch_bounds__(256, 1)
void gemm_kernel(const float* __restrict__ Hm, const float* __restrict__ W) {
    extern __shared__ float sm[];
    float* As = sm;              // [128][128] (row, k)
    float* Bs = sm + 128 * 128;  // [128][128] (k, col)

    const int tid  = threadIdx.x;
    const int row0 = blockIdx.x * 128;

#pragma unroll
    for (int i = 0; i < 16; i++) {
        int fi = (i * 256 + tid) * 4;
        *(float4*)&Bs[fi] = *(const float4*)&W[fi];
    }
#pragma unroll
    for (int i = 0; i < 16; i++) {
        int idx4 = i * 256 + tid;
        int r = idx4 >> 5;
        int c = (idx4 & 31) * 4;
        float4 v = make_float4(0.f, 0.f, 0.f, 0.f);
        int gr = row0 + r;
        if (gr < ROWS_) v = *(const float4*)&Hm[(size_t)gr * D_ + c];
        *(float4*)&As[r * D_ + c] = v;
    }
    __syncthreads();

    const int tx = tid & 15;   // 16 col-groups of 8
    const int ty = tid >> 4;   // 16 row-groups of 8

    unsigned long long acc[8][4];
#pragma unroll
    for (int i = 0; i < 8; i++)
#pragma unroll
        for (int j = 0; j < 4; j++) acc[i][j] = 0ull;

#pragma unroll 4
    for (int k = 0; k < 128; k++) {
        unsigned long long bp[4];
        *(ulonglong2*)&bp[0] = *(ulonglong2*)&Bs[k * 128 + tx * 8];
        *(ulonglong2*)&bp[2] = *(ulonglong2*)&Bs[k * 128 + tx * 8 + 4];
        unsigned long long ap[8];
#pragma unroll
        for (int i = 0; i < 8; i++) ap[i] = pack2(As[(ty * 8 + i) * D_ + k]);
#pragma unroll
        for (int i = 0; i < 8; i++)
#pragma unroll
            for (int j = 0; j < 4; j++) FMA2(acc[i][j], ap[i], bp[j], acc[i][j]);
    }

#pragma unroll
    for (int i = 0; i < 8; i++) {
        int gr = row0 + ty * 8 + i;
        if (gr < ROWS_) {
            int b = (gr >= N_) ? 1 : 0;
            int n = gr - b * N_;
            __half2 h0 = __float22half2_rn(*(float2*)&acc[i][0]);
            __half2 h1 = __float22half2_rn(*(float2*)&acc[i][1]);
            __half2 h2 = __float22half2_rn(*(float2*)&acc[i][2]);
            __half2 h3 = __float22half2_rn(*(float2*)&acc[i][3]);
            uint4 v;
            v.x = *(unsigned int*)&h0;
            v.y = *(unsigned int*)&h1;
            v.z = *(unsigned int*)&h2;
            v.w = *(unsigned int*)&h3;
            *(uint4*)(g_mh + (size_t)n * 256 + b * 128 + tx * 8) = v;
        }
    }
}

// ---------------------------------------------------------------------------
// Kernel 6: fused gather-accumulate + gelu + residual + LayerNorm.
// One warp per dst node. Per edge: one contiguous 512B read (both batches).
// Lanes 0-15 own batch 0 (8 features each), lanes 16-31 own batch 1.
// (R6 form — the explicitly MLP-batched variant measured slower.)
// ---------------------------------------------------------------------------
__device__ __forceinline__ float gelu_exact(float v) {
    return 0.5f * v * (1.0f + erff(v * 0.70710678118654752f));
}

// reduce across the 16-lane half-group (xor offsets < 16 stay in-group)
__device__ __forceinline__ float half_sum(float s) {
#pragma unroll
    for (int o = 8; o > 0; o >>= 1) s += __shfl_xor_sync(0xffffffffu, s, o);
    return s;
}

__global__ __launch_bounds__(256)
void gather_ln_kernel(const float* __restrict__ Hm,
                      const float* __restrict__ gamma,
                      const float* __restrict__ beta,
                      float* __restrict__ out) {
    const int node = (blockIdx.x * blockDim.x + threadIdx.x) >> 5;
    const int lane = threadIdx.x & 31;
    if (node >= N_) return;

    const int beg = g_offset[node];
    const int end = g_offset[node + 1];
    const size_t laneoff = (size_t)lane * 8;

    float a0 = 0.f, a1 = 0.f, a2 = 0.f, a3 = 0.f;
    float a4 = 0.f, a5 = 0.f, a6 = 0.f, a7 = 0.f;

    for (int base = beg; base < end; base += 32) {
        int k = base + lane;
        int myS = (k < end) ? g_esrc[k] : 0;
        int cnt = min(32, end - base);
#pragma unroll 4
        for (int j = 0; j < cnt; j++) {
            int s = __shfl_sync(0xffffffffu, myS, j);
            uint4 v = *(const uint4*)(g_mh + (size_t)s * 256 + laneoff);
            float2 f0 = __half22float2(*(__half2*)&v.x);
            float2 f1 = __half22float2(*(__half2*)&v.y);
            float2 f2 = __half22float2(*(__half2*)&v.z);
            float2 f3 = __half22float2(*(__half2*)&v.w);
            a0 += f0.x; a1 += f0.y; a2 += f1.x; a3 += f1.y;
            a4 += f2.x; a5 += f2.y; a6 += f3.x; a7 += f3.y;
        }
    }

    // lane -> (batch, feature group)
    const int bsel = lane >> 4;          // 0 or 1
    const int fg   = lane & 15;          // 16 groups of 8 features
    const size_t rowoff = (size_t)(bsel * N_ + node) * D_ + fg * 8;

    float4 h0 = *(const float4*)(Hm + rowoff);
    float4 h1 = *(const float4*)(Hm + rowoff + 4);

    float x0 = h0.x + gelu_exact(a0);
    float x1 = h0.y + gelu_exact(a1);
    float x2 = h0.z + gelu_exact(a2);
    float x3 = h0.w + gelu_exact(a3);
    float x4 = h1.x + gelu_exact(a4);
    float x5 = h1.y + gelu_exact(a5);
    float x6 = h1.z + gelu_exact(a6);
    float x7 = h1.w + gelu_exact(a7);

    float mean = half_sum(x0 + x1 + x2 + x3 + x4 + x5 + x6 + x7) * (1.0f / D_);

    float d0 = x0 - mean, d1 = x1 - mean, d2 = x2 - mean, d3 = x3 - mean;
    float d4 = x4 - mean, d5 = x5 - mean, d6 = x6 - mean, d7 = x7 - mean;
    float var = half_sum(d0 * d0 + d1 * d1 + d2 * d2 + d3 * d3 +
                         d4 * d4 + d5 * d5 + d6 * d6 + d7 * d7) * (1.0f / D_);
    float inv = rsqrtf(var + 1e-5f);

    float4 g0 = *(const float4*)(gamma + fg * 8);
    float4 g1 = *(const float4*)(gamma + fg * 8 + 4);
    float4 b0 = *(const float4*)(beta + fg * 8);
    float4 b1 = *(const float4*)(beta + fg * 8 + 4);

    float4 o0, o1;
    o0.x = d0 * inv * g0.x + b0.x;
    o0.y = d1 * inv * g0.y + b0.y;
    o0.z = d2 * inv * g0.z + b0.z;
    o0.w = d3 * inv * g0.w + b0.w;
    o1.x = d4 * inv * g1.x + b1.x;
    o1.y = d5 * inv * g1.y + b1.y;
    o1.z = d6 * inv * g1.z + b1.z;
    o1.w = d7 * inv * g1.w + b1.w;
    *(float4*)(out + rowoff)     = o0;
    *(float4*)(out + rowoff + 4) = o1;
}

// ---------------------------------------------------------------------------
// Launcher: fork GEMM onto a side stream, CSR build on the main stream,
// join before the fused gather+LN. Capture-safe fork/join via events.
// ---------------------------------------------------------------------------
extern "C" void kernel_launch(void* const* d_in, const int* in_sizes, int n_in,
                              void* d_out, int out_size) {
    const float* H     = (const float*)d_in[0];
    const void*  src   = d_in[1];
    const void*  dst   = d_in[2];
    const float* W     = (const float*)d_in[3];
    const float* gamma = (const float*)d_in[4];
    const float* beta  = (const float*)d_in[5];
    float*       out   = (float*)d_out;

    (void)in_sizes; (void)n_in; (void)out_size;

    cudaFuncSetAttribute(gemm_kernel,
                         cudaFuncAttributeMaxDynamicSharedMemorySize,
                         128 * 1024);

    // Host-side handles only (no device memory). Created per call; not
    // destroyed while capture is active (tiny host-side leak across the
    // ~2 calls the harness makes is intentional and legal).
    cudaStream_t side;
    cudaStreamCreateWithFlags(&side, cudaStreamNonBlocking);
    cudaEvent_t eFork, eJoin;
    cudaEventCreateWithFlags(&eFork, cudaEventDisableTiming);
    cudaEventCreateWithFlags(&eJoin, cudaEventDisableTiming);

    // 0) index dtype probe (main stream)
    detect_idx_kernel<<<1, 32>>>((const unsigned int*)src,
                                 (const unsigned int*)dst);

    // fork: side stream runs the GEMM concurrently with the CSR build
    cudaEventRecord(eFork, 0);
    cudaStreamWaitEvent(side, eFork, 0);
    gemm_kernel<<<(ROWS_ + 127) / 128, 256, 128 * 1024, side>>>(H, W);
    cudaEventRecord(eJoin, side);

    // main stream: CSR build
    zero_count_kernel<<<(N_ + 255) / 256, 256>>>();
    hist_kernel<<<(E_ / 4 + 255) / 256, 256>>>(dst);
    scan_kernel<<<1, 1024>>>();
    fill_kernel<<<(E_ / 4 + 255) / 256, 256>>>(src, dst);

    // join: gather needs both the CSR and the GEMM output
    cudaStreamWaitEvent(0, eJoin, 0);
    gather_ln_kernel<<<(N_ * 32 + 255) / 256, 256>>>(H, gamma, beta, out);
}

// round 10
// speedup vs baseline: 1.7603x; 1.6238x over previous
#include <cuda_runtime.h>
#include <cuda_fp16.h>
#include <math.h>

// Problem shape (fixed by dataset)
#define B_    2
#define N_    50000
#define D_    128
#define E_    800000
#define ROWS_ (B_ * N_)   // 100000 rows when H viewed as [B*N, D]
#define CAP_  64          // per-node bucket capacity (P(deg>=64) ~ 2e-18/node)

// Scratch: device globals (no allocation allowed)
// m stored fp16, node-interleaved: g_mh[node*256 + batch*128 + d]
__device__ __half g_mh[(size_t)N_ * 256];
__device__ int    g_idx_is64;                 // 1 if src/dst are int64, else int32
__device__ int    g_count[N_];                // per-node degree / fill cursor
                                              // (zero-init at load; gather re-zeros
                                              //  it for the next replay)
__device__ int    g_bucket[(size_t)N_ * CAP_]; // edge src ids, bucketed by dst

// ---------------------------------------------------------------------------
// Kernel 0: detect index dtype (graph-safe, deterministic).
// int64 indices < 50000 have zero odd 32-bit words.
// ---------------------------------------------------------------------------
__global__ void detect_idx_kernel(const unsigned int* __restrict__ src_w,
                                  const unsigned int* __restrict__ dst_w) {
    if (threadIdx.x == 0 && blockIdx.x == 0) {
        unsigned int acc = 0;
#pragma unroll 8
        for (int i = 0; i < 64; i++) {
            acc |= src_w[2 * i + 1];
            acc |= dst_w[2 * i + 1];
        }
        g_idx_is64 = (acc == 0u) ? 1 : 0;
    }
}

// ---------------------------------------------------------------------------
// Kernel 1: bucket fill (4 edges/thread, vector loads).
//   pos = count[d]++;  bucket[d*CAP + pos] = s
// g_count must be all-zero on entry (module init / previous gather pass).
// ---------------------------------------------------------------------------
__global__ void fill_kernel(const void* __restrict__ src,
                            const void* __restrict__ dst) {
    int i = blockIdx.x * blockDim.x + threadIdx.x;
    if (i * 4 >= E_) return;
    int s0, s1, s2, s3, d0, d1, d2, d3;
    if (g_idx_is64) {
        longlong2 sa = ((const longlong2*)src)[i * 2];
        longlong2 sb = ((const longlong2*)src)[i * 2 + 1];
        longlong2 da = ((const longlong2*)dst)[i * 2];
        longlong2 db = ((const longlong2*)dst)[i * 2 + 1];
        s0 = (int)sa.x; s1 = (int)sa.y; s2 = (int)sb.x; s3 = (int)sb.y;
        d0 = (int)da.x; d1 = (int)da.y; d2 = (int)db.x; d3 = (int)db.y;
    } else {
        int4 sv = ((const int4*)src)[i];
        int4 dv = ((const int4*)dst)[i];
        s0 = sv.x; s1 = sv.y; s2 = sv.z; s3 = sv.w;
        d0 = dv.x; d1 = dv.y; d2 = dv.z; d3 = dv.w;
    }
    int p0 = atomicAdd(&g_count[d0], 1);
    int p1 = atomicAdd(&g_count[d1], 1);
    int p2 = atomicAdd(&g_count[d2], 1);
    int p3 = atomicAdd(&g_count[d3], 1);
    if (p0 < CAP_) g_bucket[d0 * CAP_ + p0] = s0;
    if (p1 < CAP_) g_bucket[d1 * CAP_ + p1] = s1;
    if (p2 < CAP_) g_bucket[d2 * CAP_ + p2] = s2;
    if (p3 < CAP_) g_bucket[d3 * CAP_ + p3] = s3;
}

// ---------------------------------------------------------------------------
// Kernel 2: SGEMM  m[r,:] = H[r,:] @ W, packed f32x2 FMAs, fp16 output
// into node-interleaved layout. Block tile 128x128, 256 threads, 8x8/thread.
// ---------------------------------------------------------------------------
__device__ __forceinline__ unsigned long long pack2(float v) {
    unsigned long long r;
    unsigned int u = __float_as_uint(v);
    asm("mov.b64 %0, {%1, %1};" : "=l"(r) : "r"(u));
    return r;
}
#define FMA2(d, a, b, c) \
    asm("fma.rn.f32x2 %0, %1, %2, %3;" : "=l"(d) : "l"(a), "l"(b), "l"(c))

__global__ __launch_bounds__(256, 1)
void gemm_kernel(const float* __restrict__ Hm, const float* __restrict__ W) {
    extern __shared__ float sm[];
    float* As = sm;              // [128][128] (row, k)
    float* Bs = sm + 128 * 128;  // [128][128] (k, col)

    const int tid  = threadIdx.x;
    const int row0 = blockIdx.x * 128;

#pragma unroll
    for (int i = 0; i < 16; i++) {
        int fi = (i * 256 + tid) * 4;
        *(float4*)&Bs[fi] = *(const float4*)&W[fi];
    }
#pragma unroll
    for (int i = 0; i < 16; i++) {
        int idx4 = i * 256 + tid;
        int r = idx4 >> 5;
        int c = (idx4 & 31) * 4;
        float4 v = make_float4(0.f, 0.f, 0.f, 0.f);
        int gr = row0 + r;
        if (gr < ROWS_) v = *(const float4*)&Hm[(size_t)gr * D_ + c];
        *(float4*)&As[r * D_ + c] = v;
    }
    __syncthreads();

    const int tx = tid & 15;   // 16 col-groups of 8
    const int ty = tid >> 4;   // 16 row-groups of 8

    unsigned long long acc[8][4];
#pragma unroll
    for (int i = 0; i < 8; i++)
#pragma unroll
        for (int j = 0; j < 4; j++) acc[i][j] = 0ull;

#pragma unroll 4
    for (int k = 0; k < 128; k++) {
        unsigned long long bp[4];
        *(ulonglong2*)&bp[0] = *(ulonglong2*)&Bs[k * 128 + tx * 8];
        *(ulonglong2*)&bp[2] = *(ulonglong2*)&Bs[k * 128 + tx * 8 + 4];
        unsigned long long ap[8];
#pragma unroll
        for (int i = 0; i < 8; i++) ap[i] = pack2(As[(ty * 8 + i) * D_ + k]);
#pragma unroll
        for (int i = 0; i < 8; i++)
#pragma unroll
            for (int j = 0; j < 4; j++) FMA2(acc[i][j], ap[i], bp[j], acc[i][j]);
    }

#pragma unroll
    for (int i = 0; i < 8; i++) {
        int gr = row0 + ty * 8 + i;
        if (gr < ROWS_) {
            int b = (gr >= N_) ? 1 : 0;
            int n = gr - b * N_;
            __half2 h0 = __float22half2_rn(*(float2*)&acc[i][0]);
            __half2 h1 = __float22half2_rn(*(float2*)&acc[i][1]);
            __half2 h2 = __float22half2_rn(*(float2*)&acc[i][2]);
            __half2 h3 = __float22half2_rn(*(float2*)&acc[i][3]);
            uint4 v;
            v.x = *(unsigned int*)&h0;
            v.y = *(unsigned int*)&h1;
            v.z = *(unsigned int*)&h2;
            v.w = *(unsigned int*)&h3;
            *(uint4*)(g_mh + (size_t)n * 256 + b * 128 + tx * 8) = v;
        }
    }
}

// ---------------------------------------------------------------------------
// Kernel 3: fused gather-accumulate + gelu + residual + LayerNorm.
// One warp per dst node. Per edge: one contiguous 512B read (both batches).
// Lanes 0-15 own batch 0 (8 features each), lanes 16-31 own batch 1.
// Edge ids come from the node's fixed-cap bucket (<= 64 entries, 2 lane-loads).
// Also re-zeros g_count[node] for the next replay (graph-deterministic).
// ---------------------------------------------------------------------------
__device__ __forceinline__ float gelu_exact(float v) {
    return 0.5f * v * (1.0f + erff(v * 0.70710678118654752f));
}

// reduce across the 16-lane half-group (xor offsets < 16 stay in-group)
__device__ __forceinline__ float half_sum(float s) {
#pragma unroll
    for (int o = 8; o > 0; o >>= 1) s += __shfl_xor_sync(0xffffffffu, s, o);
    return s;
}

__global__ __launch_bounds__(256)
void gather_ln_kernel(const float* __restrict__ Hm,
                      const float* __restrict__ gamma,
                      const float* __restrict__ beta,
                      float* __restrict__ out) {
    const int node = (blockIdx.x * blockDim.x + threadIdx.x) >> 5;
    const int lane = threadIdx.x & 31;
    if (node >= N_) return;

    int deg = g_count[node];
    if (deg > CAP_) deg = CAP_;

    // hoist the residual-row loads (DRAM latency overlaps the edge loop)
    const int bsel = lane >> 4;          // 0 or 1
    const int fg   = lane & 15;          // 16 groups of 8 features
    const size_t rowoff = (size_t)(bsel * N_ + node) * D_ + fg * 8;
    float4 h0 = *(const float4*)(Hm + rowoff);
    float4 h1 = *(const float4*)(Hm + rowoff + 4);

    // bucket ids: up to 64 contiguous ints -> two lane-coalesced loads
    const int* bucket = g_bucket + (size_t)node * CAP_;
    int id0 = (lane      < deg) ? bucket[lane]      : 0;
    int id1 = (lane + 32 < deg) ? bucket[lane + 32] : 0;

    // reset for next replay
    if (lane == 0) g_count[node] = 0;

    const size_t laneoff = (size_t)lane * 8;
    float a0 = 0.f, a1 = 0.f, a2 = 0.f, a3 = 0.f;
    float a4 = 0.f, a5 = 0.f, a6 = 0.f, a7 = 0.f;

    int c0 = min(deg, 32);
#pragma unroll 4
    for (int j = 0; j < c0; j++) {
        int s = __shfl_sync(0xffffffffu, id0, j);
        uint4 v = *(const uint4*)(g_mh + (size_t)s * 256 + laneoff);
        float2 f0 = __half22float2(*(__half2*)&v.x);
        float2 f1 = __half22float2(*(__half2*)&v.y);
        float2 f2 = __half22float2(*(__half2*)&v.z);
        float2 f3 = __half22float2(*(__half2*)&v.w);
        a0 += f0.x; a1 += f0.y; a2 += f1.x; a3 += f1.y;
        a4 += f2.x; a5 += f2.y; a6 += f3.x; a7 += f3.y;
    }
    int c1 = deg - 32;
#pragma unroll 4
    for (int j = 0; j < c1; j++) {
        int s = __shfl_sync(0xffffffffu, id1, j);
        uint4 v = *(const uint4*)(g_mh + (size_t)s * 256 + laneoff);
        float2 f0 = __half22float2(*(__half2*)&v.x);
        float2 f1 = __half22float2(*(__half2*)&v.y);
        float2 f2 = __half22float2(*(__half2*)&v.z);
        float2 f3 = __half22float2(*(__half2*)&v.w);
        a0 += f0.x; a1 += f0.y; a2 += f1.x; a3 += f1.y;
        a4 += f2.x; a5 += f2.y; a6 += f3.x; a7 += f3.y;
    }

    float x0 = h0.x + gelu_exact(a0);
    float x1 = h0.y + gelu_exact(a1);
    float x2 = h0.z + gelu_exact(a2);
    float x3 = h0.w + gelu_exact(a3);
    float x4 = h1.x + gelu_exact(a4);
    float x5 = h1.y + gelu_exact(a5);
    float x6 = h1.z + gelu_exact(a6);
    float x7 = h1.w + gelu_exact(a7);

    float mean = half_sum(x0 + x1 + x2 + x3 + x4 + x5 + x6 + x7) * (1.0f / D_);

    float d0 = x0 - mean, d1 = x1 - mean, d2 = x2 - mean, d3 = x3 - mean;
    float d4 = x4 - mean, d5 = x5 - mean, d6 = x6 - mean, d7 = x7 - mean;
    float var = half_sum(d0 * d0 + d1 * d1 + d2 * d2 + d3 * d3 +
                         d4 * d4 + d5 * d5 + d6 * d6 + d7 * d7) * (1.0f / D_);
    float inv = rsqrtf(var + 1e-5f);

    float4 g0 = *(const float4*)(gamma + fg * 8);
    float4 g1 = *(const float4*)(gamma + fg * 8 + 4);
    float4 b0 = *(const float4*)(beta + fg * 8);
    float4 b1 = *(const float4*)(beta + fg * 8 + 4);

    float4 o0, o1;
    o0.x = d0 * inv * g0.x + b0.x;
    o0.y = d1 * inv * g0.y + b0.y;
    o0.z = d2 * inv * g0.z + b0.z;
    o0.w = d3 * inv * g0.w + b0.w;
    o1.x = d4 * inv * g1.x + b1.x;
    o1.y = d5 * inv * g1.y + b1.y;
    o1.z = d6 * inv * g1.z + b1.z;
    o1.w = d7 * inv * g1.w + b1.w;
    *(float4*)(out + rowoff)     = o0;
    *(float4*)(out + rowoff + 4) = o1;
}

// ---------------------------------------------------------------------------
// Launcher: fork GEMM immediately (independent of the index probe); main
// stream runs probe -> bucket fill; join before the fused gather+LN.
// ---------------------------------------------------------------------------
extern "C" void kernel_launch(void* const* d_in, const int* in_sizes, int n_in,
                              void* d_out, int out_size) {
    const float* H     = (const float*)d_in[0];
    const void*  src   = d_in[1];
    const void*  dst   = d_in[2];
    const float* W     = (const float*)d_in[3];
    const float* gamma = (const float*)d_in[4];
    const float* beta  = (const float*)d_in[5];
    float*       out   = (float*)d_out;

    (void)in_sizes; (void)n_in; (void)out_size;

    cudaFuncSetAttribute(gemm_kernel,
                         cudaFuncAttributeMaxDynamicSharedMemorySize,
                         128 * 1024);

    // Host-side handles only (no device memory).
    cudaStream_t side;
    cudaStreamCreateWithFlags(&side, cudaStreamNonBlocking);
    cudaEvent_t eFork, eJoin;
    cudaEventCreateWithFlags(&eFork, cudaEventDisableTiming);
    cudaEventCreateWithFlags(&eJoin, cudaEventDisableTiming);

    // fork first: GEMM does not depend on the index probe
    cudaEventRecord(eFork, 0);
    cudaStreamWaitEvent(side, eFork, 0);
    gemm_kernel<<<(ROWS_ + 127) / 128, 256, 128 * 1024, side>>>(H, W);
    cudaEventRecord(eJoin, side);

    // main stream: probe -> bucket fill (g_count is zero from module init /
    // from the previous gather pass)
    detect_idx_kernel<<<1, 32>>>((const unsigned int*)src,
                                 (const unsigned int*)dst);
    fill_kernel<<<(E_ / 4 + 255) / 256, 256>>>(src, dst);

    // join: gather needs both the buckets and the GEMM output
    cudaStreamWaitEvent(0, eJoin, 0);
    gather_ln_kernel<<<(N_ * 32 + 255) / 256, 256>>>(H, gamma, beta, out);
}

// round 12
// speedup vs baseline: 2.2474x; 1.2767x over previous
#include <cuda_runtime.h>
#include <cuda_fp16.h>
#include <math.h>
#include <cstdint>

// Problem shape (fixed by dataset)
#define B_    2
#define N_    50000
#define D_    128
#define E_    800000
#define ROWS_ (B_ * N_)   // 100000 rows when H viewed as [B*N, D]
#define CAP_  64          // per-node bucket capacity (P(deg>=64) ~ 2e-18/node)

// Scratch: device globals (no allocation allowed)
// m stored fp16, node-interleaved: g_mh[node*256 + batch*128 + d]
__device__ __half g_mh[(size_t)N_ * 256];
__device__ int    g_idx_is64;
__device__ int    g_count[N_];                 // degree/cursor; re-zeroed by gather
__device__ int    g_bucket[(size_t)N_ * CAP_]; // edge src ids bucketed by dst

// ===========================================================================
// Kernel 0: detect index dtype (graph-safe, deterministic).
// ===========================================================================
__global__ void detect_idx_kernel(const unsigned int* __restrict__ src_w,
                                  const unsigned int* __restrict__ dst_w) {
    if (threadIdx.x == 0 && blockIdx.x == 0) {
        unsigned int acc = 0;
#pragma unroll 8
        for (int i = 0; i < 64; i++) {
            acc |= src_w[2 * i + 1];
            acc |= dst_w[2 * i + 1];
        }
        g_idx_is64 = (acc == 0u) ? 1 : 0;
    }
}

// ===========================================================================
// Kernel 1: bucket fill (4 edges/thread, vector loads).
// ===========================================================================
__global__ void fill_kernel(const void* __restrict__ src,
                            const void* __restrict__ dst) {
    int i = blockIdx.x * blockDim.x + threadIdx.x;
    if (i * 4 >= E_) return;
    int s0, s1, s2, s3, d0, d1, d2, d3;
    if (g_idx_is64) {
        longlong2 sa = ((const longlong2*)src)[i * 2];
        longlong2 sb = ((const longlong2*)src)[i * 2 + 1];
        longlong2 da = ((const longlong2*)dst)[i * 2];
        longlong2 db = ((const longlong2*)dst)[i * 2 + 1];
        s0 = (int)sa.x; s1 = (int)sa.y; s2 = (int)sb.x; s3 = (int)sb.y;
        d0 = (int)da.x; d1 = (int)da.y; d2 = (int)db.x; d3 = (int)db.y;
    } else {
        int4 sv = ((const int4*)src)[i];
        int4 dv = ((const int4*)dst)[i];
        s0 = sv.x; s1 = sv.y; s2 = sv.z; s3 = sv.w;
        d0 = dv.x; d1 = dv.y; d2 = dv.z; d3 = dv.w;
    }
    int p0 = atomicAdd(&g_count[d0], 1);
    int p1 = atomicAdd(&g_count[d1], 1);
    int p2 = atomicAdd(&g_count[d2], 1);
    int p3 = atomicAdd(&g_count[d3], 1);
    if (p0 < CAP_) g_bucket[d0 * CAP_ + p0] = s0;
    if (p1 < CAP_) g_bucket[d1 * CAP_ + p1] = s1;
    if (p2 < CAP_) g_bucket[d2 * CAP_ + p2] = s2;
    if (p3 < CAP_) g_bucket[d3 * CAP_ + p3] = s3;
}

// ===========================================================================
// Kernel 2: HMMA fp16 GEMM  m = H @ W  -> g_mh (fp16, node-interleaved).
// mma.sync.aligned.m16n8k16.f32.f16.f16.f32 (plain PTX, sm_80+; no tcgen05).
// CTA tile 128x128 (K=128), 8 warps, warp tile 64x32 (4 m-tiles x 4 n-tiles).
// A staged row-major fp16 (pad 8), B staged as Bt[n][k] = W[k][n] (pad 8).
// ===========================================================================
#define APAD   8
#define ASTR   (128 + APAD)     // halves per A/B smem row
#define SM_A_HALVES (128 * ASTR)
#define SM_TOT_BYTES (2 * SM_A_HALVES * 2)   // A + B tiles, fp16

__device__ __forceinline__ void mma16816(float* c, const uint32_t* a,
                                         const uint32_t* b) {
    asm volatile(
        "mma.sync.aligned.m16n8k16.row.col.f32.f16.f16.f32 "
        "{%0,%1,%2,%3}, {%4,%5,%6,%7}, {%8,%9}, {%0,%1,%2,%3};"
        : "+f"(c[0]), "+f"(c[1]), "+f"(c[2]), "+f"(c[3])
        : "r"(a[0]), "r"(a[1]), "r"(a[2]), "r"(a[3]), "r"(b[0]), "r"(b[1]));
}

__global__ __launch_bounds__(256)
void gemm_hmma_kernel(const float* __restrict__ Hm, const float* __restrict__ W) {
    extern __shared__ __half sm[];
    __half* As = sm;                 // [128][ASTR] row-major (row, k)
    __half* Bt = sm + SM_A_HALVES;   // [128][ASTR] (n, k)  Bt[n][k] = W[k][n]

    const int tid  = threadIdx.x;
    const int wid  = tid >> 5;
    const int lane = tid & 31;
    const int gid  = lane >> 2;      // 0..7
    const int tg   = lane & 3;       // 0..3
    const int row0 = blockIdx.x * 128;

    // Stage A: 4096 float4 reads, fp32 -> fp16
#pragma unroll
    for (int it = 0; it < 16; it++) {
        int idx4 = it * 256 + tid;          // 0..4095
        int r = idx4 >> 5;
        int c = (idx4 & 31) * 4;
        int gr = row0 + r;
        float4 v = make_float4(0.f, 0.f, 0.f, 0.f);
        if (gr < ROWS_) v = *(const float4*)&Hm[(size_t)gr * D_ + c];
        __half2 h01 = __float22half2_rn(make_float2(v.x, v.y));
        __half2 h23 = __float22half2_rn(make_float2(v.z, v.w));
        *(__half2*)&As[r * ASTR + c]     = h01;
        *(__half2*)&As[r * ASTR + c + 2] = h23;
    }
    // Stage B transposed: Bt[n][k] = W[k][n]
#pragma unroll
    for (int it = 0; it < 16; it++) {
        int idx4 = it * 256 + tid;
        int k = idx4 >> 5;
        int n = (idx4 & 31) * 4;
        float4 v = *(const float4*)&W[k * 128 + n];
        Bt[(n    ) * ASTR + k] = __float2half_rn(v.x);
        Bt[(n + 1) * ASTR + k] = __float2half_rn(v.y);
        Bt[(n + 2) * ASTR + k] = __float2half_rn(v.z);
        Bt[(n + 3) * ASTR + k] = __float2half_rn(v.w);
    }
    __syncthreads();

    const int wr = wid >> 2;         // 0..1 : row block of 64
    const int wc = wid & 3;          // 0..3 : col block of 32

    float acc[16][4];
#pragma unroll
    for (int i = 0; i < 16; i++)
#pragma unroll
        for (int j = 0; j < 4; j++) acc[i][j] = 0.f;

#pragma unroll
    for (int ks = 0; ks < 8; ks++) {
        const int k0 = ks * 16;
        uint32_t af[4][4], bf[4][2];
#pragma unroll
        for (int mt = 0; mt < 4; mt++) {
            int r = wr * 64 + mt * 16 + gid;
            af[mt][0] = *(const uint32_t*)&As[(r    ) * ASTR + k0 + tg * 2];
            af[mt][1] = *(const uint32_t*)&As[(r + 8) * ASTR + k0 + tg * 2];
            af[mt][2] = *(const uint32_t*)&As[(r    ) * ASTR + k0 + tg * 2 + 8];
            af[mt][3] = *(const uint32_t*)&As[(r + 8) * ASTR + k0 + tg * 2 + 8];
        }
#pragma unroll
        for (int nt = 0; nt < 4; nt++) {
            int n = wc * 32 + nt * 8 + gid;
            bf[nt][0] = *(const uint32_t*)&Bt[n * ASTR + k0 + tg * 2];
            bf[nt][1] = *(const uint32_t*)&Bt[n * ASTR + k0 + tg * 2 + 8];
        }
#pragma unroll
        for (int mt = 0; mt < 4; mt++)
#pragma unroll
            for (int nt = 0; nt < 4; nt++)
                mma16816(acc[mt * 4 + nt], af[mt], bf[nt]);
    }

    // Epilogue: write fp16 pairs into g_mh (node-interleaved).
#pragma unroll
    for (int mt = 0; mt < 4; mt++) {
#pragma unroll
        for (int half = 0; half < 2; half++) {
            int gr = row0 + wr * 64 + mt * 16 + gid + half * 8;
            if (gr >= ROWS_) continue;
            int b = (gr >= N_) ? 1 : 0;
            int n = gr - b * N_;
            __half* drow = g_mh + (size_t)n * 256 + b * 128;
#pragma unroll
            for (int nt = 0; nt < 4; nt++) {
                float* c = acc[mt * 4 + nt];
                float2 f = half ? make_float2(c[2], c[3])
                                : make_float2(c[0], c[1]);
                __half2 h = __float22half2_rn(f);
                *(__half2*)(drow + wc * 32 + nt * 8 + tg * 2) = h;
            }
        }
    }
}

// ===========================================================================
// Kernel 3: fused gather + gelu + residual + LayerNorm (unchanged from R10).
// ===========================================================================
__device__ __forceinline__ float gelu_exact(float v) {
    return 0.5f * v * (1.0f + erff(v * 0.70710678118654752f));
}
__device__ __forceinline__ float half_sum(float s) {
#pragma unroll
    for (int o = 8; o > 0; o >>= 1) s += __shfl_xor_sync(0xffffffffu, s, o);
    return s;
}

__global__ __launch_bounds__(256)
void gather_ln_kernel(const float* __restrict__ Hm,
                      const float* __restrict__ gamma,
                      const float* __restrict__ beta,
                      float* __restrict__ out) {
    const int node = (blockIdx.x * blockDim.x + threadIdx.x) >> 5;
    const int lane = threadIdx.x & 31;
    if (node >= N_) return;

    int deg = g_count[node];
    if (deg > CAP_) deg = CAP_;

    const int bsel = lane >> 4;
    const int fg   = lane & 15;
    const size_t rowoff = (size_t)(bsel * N_ + node) * D_ + fg * 8;
    float4 h0 = *(const float4*)(Hm + rowoff);
    float4 h1 = *(const float4*)(Hm + rowoff + 4);

    const int* bucket = g_bucket + (size_t)node * CAP_;
    int id0 = (lane      < deg) ? bucket[lane]      : 0;
    int id1 = (lane + 32 < deg) ? bucket[lane + 32] : 0;

    if (lane == 0) g_count[node] = 0;  // reset for next replay

    const size_t laneoff = (size_t)lane * 8;
    float a0 = 0.f, a1 = 0.f, a2 = 0.f, a3 = 0.f;
    float a4 = 0.f, a5 = 0.f, a6 = 0.f, a7 = 0.f;

    int c0 = min(deg, 32);
#pragma unroll 4
    for (int j = 0; j < c0; j++) {
        int s = __shfl_sync(0xffffffffu, id0, j);
        uint4 v = *(const uint4*)(g_mh + (size_t)s * 256 + laneoff);
        float2 f0 = __half22float2(*(__half2*)&v.x);
        float2 f1 = __half22float2(*(__half2*)&v.y);
        float2 f2 = __half22float2(*(__half2*)&v.z);
        float2 f3 = __half22float2(*(__half2*)&v.w);
        a0 += f0.x; a1 += f0.y; a2 += f1.x; a3 += f1.y;
        a4 += f2.x; a5 += f2.y; a6 += f3.x; a7 += f3.y;
    }
    int c1 = deg - 32;
#pragma unroll 4
    for (int j = 0; j < c1; j++) {
        int s = __shfl_sync(0xffffffffu, id1, j);
        uint4 v = *(const uint4*)(g_mh + (size_t)s * 256 + laneoff);
        float2 f0 = __half22float2(*(__half2*)&v.x);
        float2 f1 = __half22float2(*(__half2*)&v.y);
        float2 f2 = __half22float2(*(__half2*)&v.z);
        float2 f3 = __half22float2(*(__half2*)&v.w);
        a0 += f0.x; a1 += f0.y; a2 += f1.x; a3 += f1.y;
        a4 += f2.x; a5 += f2.y; a6 += f3.x; a7 += f3.y;
    }

    float x0 = h0.x + gelu_exact(a0);
    float x1 = h0.y + gelu_exact(a1);
    float x2 = h0.z + gelu_exact(a2);
    float x3 = h0.w + gelu_exact(a3);
    float x4 = h1.x + gelu_exact(a4);
    float x5 = h1.y + gelu_exact(a5);
    float x6 = h1.z + gelu_exact(a6);
    float x7 = h1.w + gelu_exact(a7);

    float mean = half_sum(x0 + x1 + x2 + x3 + x4 + x5 + x6 + x7) * (1.0f / D_);

    float d0 = x0 - mean, d1 = x1 - mean, d2 = x2 - mean, d3 = x3 - mean;
    float d4 = x4 - mean, d5 = x5 - mean, d6 = x6 - mean, d7 = x7 - mean;
    float var = half_sum(d0 * d0 + d1 * d1 + d2 * d2 + d3 * d3 +
                         d4 * d4 + d5 * d5 + d6 * d6 + d7 * d7) * (1.0f / D_);
    float inv = rsqrtf(var + 1e-5f);

    float4 g0 = *(const float4*)(gamma + fg * 8);
    float4 g1 = *(const float4*)(gamma + fg * 8 + 4);
    float4 b0 = *(const float4*)(beta + fg * 8);
    float4 b1 = *(const float4*)(beta + fg * 8 + 4);

    float4 o0, o1;
    o0.x = d0 * inv * g0.x + b0.x;
    o0.y = d1 * inv * g0.y + b0.y;
    o0.z = d2 * inv * g0.z + b0.z;
    o0.w = d3 * inv * g0.w + b0.w;
    o1.x = d4 * inv * g1.x + b1.x;
    o1.y = d5 * inv * g1.y + b1.y;
    o1.z = d6 * inv * g1.z + b1.z;
    o1.w = d7 * inv * g1.w + b1.w;
    *(float4*)(out + rowoff)     = o0;
    *(float4*)(out + rowoff + 4) = o1;
}

// ===========================================================================
// Launcher: fork HMMA-GEMM onto side stream; probe+fill on main; join; gather.
// ===========================================================================
extern "C" void kernel_launch(void* const* d_in, const int* in_sizes, int n_in,
                              void* d_out, int out_size) {
    const float* H     = (const float*)d_in[0];
    const void*  src   = d_in[1];
    const void*  dst   = d_in[2];
    const float* W     = (const float*)d_in[3];
    const float* gamma = (const float*)d_in[4];
    const float* beta  = (const float*)d_in[5];
    float*       out   = (float*)d_out;

    (void)in_sizes; (void)n_in; (void)out_size;

    cudaFuncSetAttribute(gemm_hmma_kernel,
                         cudaFuncAttributeMaxDynamicSharedMemorySize,
                         SM_TOT_BYTES);

    cudaStream_t side;
    cudaStreamCreateWithFlags(&side, cudaStreamNonBlocking);
    cudaEvent_t eFork, eJoin;
    cudaEventCreateWithFlags(&eFork, cudaEventDisableTiming);
    cudaEventCreateWithFlags(&eJoin, cudaEventDisableTiming);

    // fork: GEMM does not depend on the index probe
    cudaEventRecord(eFork, 0);
    cudaStreamWaitEvent(side, eFork, 0);
    gemm_hmma_kernel<<<(ROWS_ + 127) / 128, 256, SM_TOT_BYTES, side>>>(H, W);
    cudaEventRecord(eJoin, side);

    // main stream: probe -> bucket fill
    detect_idx_kernel<<<1, 32>>>((const unsigned int*)src,
                                 (const unsigned int*)dst);
    fill_kernel<<<(E_ / 4 + 255) / 256, 256>>>(src, dst);

    // join: gather needs buckets + GEMM output
    cudaStreamWaitEvent(0, eJoin, 0);
    gather_ln_kernel<<<(N_ * 32 + 255) / 256, 256>>>(H, gamma, beta, out);
}

// round 13
// speedup vs baseline: 2.8061x; 1.2486x over previous
#include <cuda_runtime.h>
#include <cuda_fp16.h>
#include <math.h>
#include <cstdint>

// Problem shape (fixed by dataset)
#define B_    2
#define N_    50000
#define D_    128
#define E_    800000
#define ROWS_ (B_ * N_)   // 100000 rows when H viewed as [B*N, D]
#define CAP_  64          // per-node bucket capacity (P(deg>=64) ~ 2e-18/node)

// Scratch: device globals (no allocation allowed)
// m stored fp16, node-interleaved: g_mh[node*256 + batch*128 + d]
__device__ __half g_mh[(size_t)N_ * 256];
__device__ int    g_idx_is64;
__device__ int    g_count[N_];                 // degree/cursor; re-zeroed by gather
__device__ int    g_bucket[(size_t)N_ * CAP_]; // edge src ids bucketed by dst

// ===========================================================================
// Kernel 0: detect index dtype (graph-safe, deterministic).
// ===========================================================================
__global__ void detect_idx_kernel(const unsigned int* __restrict__ src_w,
                                  const unsigned int* __restrict__ dst_w) {
    if (threadIdx.x == 0 && blockIdx.x == 0) {
        unsigned int acc = 0;
#pragma unroll 8
        for (int i = 0; i < 64; i++) {
            acc |= src_w[2 * i + 1];
            acc |= dst_w[2 * i + 1];
        }
        g_idx_is64 = (acc == 0u) ? 1 : 0;
    }
}

// ===========================================================================
// Kernel 1: bucket fill (4 edges/thread, vector loads).
// ===========================================================================
__global__ void fill_kernel(const void* __restrict__ src,
                            const void* __restrict__ dst) {
    int i = blockIdx.x * blockDim.x + threadIdx.x;
    if (i * 4 >= E_) return;
    int s0, s1, s2, s3, d0, d1, d2, d3;
    if (g_idx_is64) {
        longlong2 sa = ((const longlong2*)src)[i * 2];
        longlong2 sb = ((const longlong2*)src)[i * 2 + 1];
        longlong2 da = ((const longlong2*)dst)[i * 2];
        longlong2 db = ((const longlong2*)dst)[i * 2 + 1];
        s0 = (int)sa.x; s1 = (int)sa.y; s2 = (int)sb.x; s3 = (int)sb.y;
        d0 = (int)da.x; d1 = (int)da.y; d2 = (int)db.x; d3 = (int)db.y;
    } else {
        int4 sv = ((const int4*)src)[i];
        int4 dv = ((const int4*)dst)[i];
        s0 = sv.x; s1 = sv.y; s2 = sv.z; s3 = sv.w;
        d0 = dv.x; d1 = dv.y; d2 = dv.z; d3 = dv.w;
    }
    int p0 = atomicAdd(&g_count[d0], 1);
    int p1 = atomicAdd(&g_count[d1], 1);
    int p2 = atomicAdd(&g_count[d2], 1);
    int p3 = atomicAdd(&g_count[d3], 1);
    if (p0 < CAP_) g_bucket[d0 * CAP_ + p0] = s0;
    if (p1 < CAP_) g_bucket[d1 * CAP_ + p1] = s1;
    if (p2 < CAP_) g_bucket[d2 * CAP_ + p2] = s2;
    if (p3 < CAP_) g_bucket[d3 * CAP_ + p3] = s3;
}

// ===========================================================================
// Kernel 2: HMMA fp16 GEMM  m = H @ W  -> g_mh (fp16, node-interleaved).
// CTA tile 128x128 (K=128), 8 warps, warp tile 64x32.
// A: [128][ASTR] row-major; B: Bt[n][k], BSTR=132 (2-way max conflicts);
// epilogue staged through smem for coalesced uint4 global stores.
// ===========================================================================
#define ASTR   136                   // halves per As/Cs row (272B, 16B-multiple)
#define BSTR   132                   // halves per Bt row (264B, 8B-multiple)
#define SM_A_HALVES (128 * ASTR)     // 17408
#define SM_B_HALVES (128 * BSTR)     // 16896
#define SM_TOT_BYTES ((SM_A_HALVES + SM_B_HALVES) * 2)   // 68608

__device__ __forceinline__ void mma16816(float* c, const uint32_t* a,
                                         const uint32_t* b) {
    asm volatile(
        "mma.sync.aligned.m16n8k16.row.col.f32.f16.f16.f32 "
        "{%0,%1,%2,%3}, {%4,%5,%6,%7}, {%8,%9}, {%0,%1,%2,%3};"
        : "+f"(c[0]), "+f"(c[1]), "+f"(c[2]), "+f"(c[3])
        : "r"(a[0]), "r"(a[1]), "r"(a[2]), "r"(a[3]), "r"(b[0]), "r"(b[1]));
}

__global__ __launch_bounds__(256)
void gemm_hmma_kernel(const float* __restrict__ Hm, const float* __restrict__ W) {
    extern __shared__ __half sm[];
    __half* As = sm;                 // [128][ASTR] (row, k); reused as Cs
    __half* Bt = sm + SM_A_HALVES;   // [128][BSTR] (n, k)  Bt[n][k] = W[k][n]

    const int tid  = threadIdx.x;
    const int wid  = tid >> 5;
    const int lane = tid & 31;
    const int gid  = lane >> 2;      // 0..7
    const int tg   = lane & 3;       // 0..3
    const int row0 = blockIdx.x * 128;

    // Stage A: 4096 float4 reads, fp32 -> fp16 (coalesced, conflict-free)
#pragma unroll
    for (int it = 0; it < 16; it++) {
        int idx4 = it * 256 + tid;          // 0..4095
        int r = idx4 >> 5;
        int c = (idx4 & 31) * 4;
        int gr = row0 + r;
        float4 v = make_float4(0.f, 0.f, 0.f, 0.f);
        if (gr < ROWS_) v = *(const float4*)&Hm[(size_t)gr * D_ + c];
        __half2 h01 = __float22half2_rn(make_float2(v.x, v.y));
        __half2 h23 = __float22half2_rn(make_float2(v.z, v.w));
        *(__half2*)&As[r * ASTR + c]     = h01;
        *(__half2*)&As[r * ASTR + c + 2] = h23;
    }
    // Stage B transposed: Bt[n][k] = W[k][n].
    // Lanes sweep n (coalesced gmem); each thread owns 4 consecutive k of one
    // n-row -> single 8B smem store; lane stride 264B = 2 banks -> <=2-way.
#pragma unroll
    for (int it = 0; it < 16; it++) {
        int idx = it * 256 + tid;            // 0..4095
        int n  = idx & 127;
        int k  = (idx >> 7) * 4;             // 0..124
        float va = W[(k    ) * 128 + n];
        float vb = W[(k + 1) * 128 + n];
        float vc = W[(k + 2) * 128 + n];
        float vd = W[(k + 3) * 128 + n];
        __half2 h01 = __float22half2_rn(make_float2(va, vb));
        __half2 h23 = __float22half2_rn(make_float2(vc, vd));
        unsigned long long packed =
            (unsigned long long)(*(uint32_t*)&h01) |
            ((unsigned long long)(*(uint32_t*)&h23) << 32);
        *(unsigned long long*)&Bt[n * BSTR + k] = packed;
    }
    __syncthreads();

    const int wr = wid >> 2;         // 0..1 : row block of 64
    const int wc = wid & 3;          // 0..3 : col block of 32

    float acc[16][4];
#pragma unroll
    for (int i = 0; i < 16; i++)
#pragma unroll
        for (int j = 0; j < 4; j++) acc[i][j] = 0.f;

#pragma unroll
    for (int ks = 0; ks < 8; ks++) {
        const int k0 = ks * 16;
        uint32_t af[4][4], bf[4][2];
#pragma unroll
        for (int mt = 0; mt < 4; mt++) {
            int r = wr * 64 + mt * 16 + gid;
            af[mt][0] = *(const uint32_t*)&As[(r    ) * ASTR + k0 + tg * 2];
            af[mt][1] = *(const uint32_t*)&As[(r + 8) * ASTR + k0 + tg * 2];
            af[mt][2] = *(const uint32_t*)&As[(r    ) * ASTR + k0 + tg * 2 + 8];
            af[mt][3] = *(const uint32_t*)&As[(r + 8) * ASTR + k0 + tg * 2 + 8];
        }
#pragma unroll
        for (int nt = 0; nt < 4; nt++) {
            int n = wc * 32 + nt * 8 + gid;
            bf[nt][0] = *(const uint32_t*)&Bt[n * BSTR + k0 + tg * 2];
            bf[nt][1] = *(const uint32_t*)&Bt[n * BSTR + k0 + tg * 2 + 8];
        }
#pragma unroll
        for (int mt = 0; mt < 4; mt++)
#pragma unroll
            for (int nt = 0; nt < 4; nt++)
                mma16816(acc[mt * 4 + nt], af[mt], bf[nt]);
    }

    // Epilogue: fragments -> Cs (reuse As; banks 4*gid+tg: conflict-free),
    // then coalesced uint4 writeout.
    __syncthreads();
    __half* Cs = As;
#pragma unroll
    for (int mt = 0; mt < 4; mt++) {
#pragma unroll
        for (int hf = 0; hf < 2; hf++) {
            int r = wr * 64 + mt * 16 + gid + hf * 8;
#pragma unroll
            for (int nt = 0; nt < 4; nt++) {
                float* c = acc[mt * 4 + nt];
                float2 f = hf ? make_float2(c[2], c[3])
                              : make_float2(c[0], c[1]);
                __half2 h = __float22half2_rn(f);
                *(__half2*)&Cs[r * ASTR + wc * 32 + nt * 8 + tg * 2] = h;
            }
        }
    }
    __syncthreads();
    // 2048 uint4 (8 halves each): 256 threads x 8 iterations, coalesced.
#pragma unroll
    for (int it = 0; it < 8; it++) {
        int idx = it * 256 + tid;     // 0..2047
        int r = idx >> 4;             // 16 uint4 per row
        int c = (idx & 15) * 8;
        int gr = row0 + r;
        if (gr < ROWS_) {
            int b = (gr >= N_) ? 1 : 0;
            int n = gr - b * N_;
            *(uint4*)(g_mh + (size_t)n * 256 + b * 128 + c) =
                *(uint4*)&Cs[r * ASTR + c];
        }
    }
}

// ===========================================================================
// Kernel 3: fused gather + gelu + residual + LayerNorm.
// Edge-paired inner loop: hadd2 two edges in fp16, one fp32 accumulate/pair.
// ===========================================================================
__device__ __forceinline__ float gelu_exact(float v) {
    return 0.5f * v * (1.0f + erff(v * 0.70710678118654752f));
}
__device__ __forceinline__ float half_sum(float s) {
#pragma unroll
    for (int o = 8; o > 0; o >>= 1) s += __shfl_xor_sync(0xffffffffu, s, o);
    return s;
}

__global__ __launch_bounds__(256)
void gather_ln_kernel(const float* __restrict__ Hm,
                      const float* __restrict__ gamma,
                      const float* __restrict__ beta,
                      float* __restrict__ out) {
    const int node = (blockIdx.x * blockDim.x + threadIdx.x) >> 5;
    const int lane = threadIdx.x & 31;
    if (node >= N_) return;

    int deg = g_count[node];
    if (deg > CAP_) deg = CAP_;

    const int bsel = lane >> 4;
    const int fg   = lane & 15;
    const size_t rowoff = (size_t)(bsel * N_ + node) * D_ + fg * 8;
    float4 h0 = *(const float4*)(Hm + rowoff);
    float4 h1 = *(const float4*)(Hm + rowoff + 4);

    const int* bucket = g_bucket + (size_t)node * CAP_;
    int id0 = (lane      < deg) ? bucket[lane]      : 0;
    int id1 = (lane + 32 < deg) ? bucket[lane + 32] : 0;

    if (lane == 0) g_count[node] = 0;  // reset for next replay

    const size_t laneoff = (size_t)lane * 8;
    float a0 = 0.f, a1 = 0.f, a2 = 0.f, a3 = 0.f;
    float a4 = 0.f, a5 = 0.f, a6 = 0.f, a7 = 0.f;

#define ACC_PAIRSUM(p0, p1, p2, p3)                         \
    do {                                                    \
        float2 f0 = __half22float2(p0);                     \
        float2 f1 = __half22float2(p1);                     \
        float2 f2 = __half22float2(p2);                     \
        float2 f3 = __half22float2(p3);                     \
        a0 += f0.x; a1 += f0.y; a2 += f1.x; a3 += f1.y;     \
        a4 += f2.x; a5 += f2.y; a6 += f3.x; a7 += f3.y;     \
    } while (0)

#define ACC_SINGLE(v)                                       \
    ACC_PAIRSUM(*(__half2*)&(v).x, *(__half2*)&(v).y,       \
                *(__half2*)&(v).z, *(__half2*)&(v).w)

    int c0 = min(deg, 32);
    int j = 0;
#pragma unroll 2
    for (; j + 2 <= c0; j += 2) {
        int s0 = __shfl_sync(0xffffffffu, id0, j);
        int s1 = __shfl_sync(0xffffffffu, id0, j + 1);
        uint4 v0 = *(const uint4*)(g_mh + (size_t)s0 * 256 + laneoff);
        uint4 v1 = *(const uint4*)(g_mh + (size_t)s1 * 256 + laneoff);
        __half2 p0 = __hadd2(*(__half2*)&v0.x, *(__half2*)&v1.x);
        __half2 p1 = __hadd2(*(__half2*)&v0.y, *(__half2*)&v1.y);
        __half2 p2 = __hadd2(*(__half2*)&v0.z, *(__half2*)&v1.z);
        __half2 p3 = __hadd2(*(__half2*)&v0.w, *(__half2*)&v1.w);
        ACC_PAIRSUM(p0, p1, p2, p3);
    }
    if (j < c0) {
        int s = __shfl_sync(0xffffffffu, id0, j);
        uint4 v = *(const uint4*)(g_mh + (size_t)s * 256 + laneoff);
        ACC_SINGLE(v);
    }
    int c1 = deg - 32;
    j = 0;
#pragma unroll 2
    for (; j + 2 <= c1; j += 2) {
        int s0 = __shfl_sync(0xffffffffu, id1, j);
        int s1 = __shfl_sync(0xffffffffu, id1, j + 1);
        uint4 v0 = *(const uint4*)(g_mh + (size_t)s0 * 256 + laneoff);
        uint4 v1 = *(const uint4*)(g_mh + (size_t)s1 * 256 + laneoff);
        __half2 p0 = __hadd2(*(__half2*)&v0.x, *(__half2*)&v1.x);
        __half2 p1 = __hadd2(*(__half2*)&v0.y, *(__half2*)&v1.y);
        __half2 p2 = __hadd2(*(__half2*)&v0.z, *(__half2*)&v1.z);
        __half2 p3 = __hadd2(*(__half2*)&v0.w, *(__half2*)&v1.w);
        ACC_PAIRSUM(p0, p1, p2, p3);
    }
    if (j >= 0 && j < c1) {
        int s = __shfl_sync(0xffffffffu, id1, j);
        uint4 v = *(const uint4*)(g_mh + (size_t)s * 256 + laneoff);
        ACC_SINGLE(v);
    }

    float x0 = h0.x + gelu_exact(a0);
    float x1 = h0.y + gelu_exact(a1);
    float x2 = h0.z + gelu_exact(a2);
    float x3 = h0.w + gelu_exact(a3);
    float x4 = h1.x + gelu_exact(a4);
    float x5 = h1.y + gelu_exact(a5);
    float x6 = h1.z + gelu_exact(a6);
    float x7 = h1.w + gelu_exact(a7);

    float mean = half_sum(x0 + x1 + x2 + x3 + x4 + x5 + x6 + x7) * (1.0f / D_);

    float d0 = x0 - mean, d1 = x1 - mean, d2 = x2 - mean, d3 = x3 - mean;
    float d4 = x4 - mean, d5 = x5 - mean, d6 = x6 - mean, d7 = x7 - mean;
    float var = half_sum(d0 * d0 + d1 * d1 + d2 * d2 + d3 * d3 +
                         d4 * d4 + d5 * d5 + d6 * d6 + d7 * d7) * (1.0f / D_);
    float inv = rsqrtf(var + 1e-5f);

    float4 g0 = *(const float4*)(gamma + fg * 8);
    float4 g1 = *(const float4*)(gamma + fg * 8 + 4);
    float4 b0 = *(const float4*)(beta + fg * 8);
    float4 b1 = *(const float4*)(beta + fg * 8 + 4);

    float4 o0, o1;
    o0.x = d0 * inv * g0.x + b0.x;
    o0.y = d1 * inv * g0.y + b0.y;
    o0.z = d2 * inv * g0.z + b0.z;
    o0.w = d3 * inv * g0.w + b0.w;
    o1.x = d4 * inv * g1.x + b1.x;
    o1.y = d5 * inv * g1.y + b1.y;
    o1.z = d6 * inv * g1.z + b1.z;
    o1.w = d7 * inv * g1.w + b1.w;
    *(float4*)(out + rowoff)     = o0;
    *(float4*)(out + rowoff + 4) = o1;
}

// ===========================================================================
// Launcher: fork HMMA-GEMM onto side stream; probe+fill on main; join; gather.
// ===========================================================================
extern "C" void kernel_launch(void* const* d_in, const int* in_sizes, int n_in,
                              void* d_out, int out_size) {
    const float* H     = (const float*)d_in[0];
    const void*  src   = d_in[1];
    const void*  dst   = d_in[2];
    const float* W     = (const float*)d_in[3];
    const float* gamma = (const float*)d_in[4];
    const float* beta  = (const float*)d_in[5];
    float*       out   = (float*)d_out;

    (void)in_sizes; (void)n_in; (void)out_size;

    cudaFuncSetAttribute(gemm_hmma_kernel,
                         cudaFuncAttributeMaxDynamicSharedMemorySize,
                         SM_TOT_BYTES);

    cudaStream_t side;
    cudaStreamCreateWithFlags(&side, cudaStreamNonBlocking);
    cudaEvent_t eFork, eJoin;
    cudaEventCreateWithFlags(&eFork, cudaEventDisableTiming);
    cudaEventCreateWithFlags(&eJoin, cudaEventDisableTiming);

    // fork: GEMM does not depend on the index probe
    cudaEventRecord(eFork, 0);
    cudaStreamWaitEvent(side, eFork, 0);
    gemm_hmma_kernel<<<(ROWS_ + 127) / 128, 256, SM_TOT_BYTES, side>>>(H, W);
    cudaEventRecord(eJoin, side);

    // main stream: probe -> bucket fill
    detect_idx_kernel<<<1, 32>>>((const unsigned int*)src,
                                 (const unsigned int*)dst);
    fill_kernel<<<(E_ / 4 + 255) / 256, 256>>>(src, dst);

    // join: gather needs buckets + GEMM output
    cudaStreamWaitEvent(0, eJoin, 0);
    gather_ln_kernel<<<(N_ * 32 + 255) / 256, 256>>>(H, gamma, beta, out);
}

// round 14
// speedup vs baseline: 2.8447x; 1.0138x over previous
#include <cuda_runtime.h>
#include <cuda_fp16.h>
#include <math.h>
#include <cstdint>

// Problem shape (fixed by dataset)
#define B_    2
#define N_    50000
#define D_    128
#define E_    800000
#define ROWS_ (B_ * N_)   // 100000 rows when H viewed as [B*N, D]
#define CAP_  64          // per-node bucket capacity (P(deg>=64) ~ 2e-18/node)

// Scratch: device globals (no allocation allowed)
// m stored fp16, node-interleaved: g_mh[node*256 + batch*128 + d]
__device__ __half g_mh[(size_t)N_ * 256];
__device__ int    g_idx_is64;
__device__ int    g_count[N_];                 // degree/cursor; re-zeroed by gather
__device__ int    g_bucket[(size_t)N_ * CAP_]; // edge src ids bucketed by dst

// ===========================================================================
// Kernel 0: detect index dtype (graph-safe, deterministic).
// ===========================================================================
__global__ void detect_idx_kernel(const unsigned int* __restrict__ src_w,
                                  const unsigned int* __restrict__ dst_w) {
    if (threadIdx.x == 0 && blockIdx.x == 0) {
        unsigned int acc = 0;
#pragma unroll 8
        for (int i = 0; i < 64; i++) {
            acc |= src_w[2 * i + 1];
            acc |= dst_w[2 * i + 1];
        }
        g_idx_is64 = (acc == 0u) ? 1 : 0;
    }
}

// ===========================================================================
// Kernel 1: bucket fill (4 edges/thread, vector loads).
// ===========================================================================
__global__ void fill_kernel(const void* __restrict__ src,
                            const void* __restrict__ dst) {
    int i = blockIdx.x * blockDim.x + threadIdx.x;
    if (i * 4 >= E_) return;
    int s0, s1, s2, s3, d0, d1, d2, d3;
    if (g_idx_is64) {
        longlong2 sa = ((const longlong2*)src)[i * 2];
        longlong2 sb = ((const longlong2*)src)[i * 2 + 1];
        longlong2 da = ((const longlong2*)dst)[i * 2];
        longlong2 db = ((const longlong2*)dst)[i * 2 + 1];
        s0 = (int)sa.x; s1 = (int)sa.y; s2 = (int)sb.x; s3 = (int)sb.y;
        d0 = (int)da.x; d1 = (int)da.y; d2 = (int)db.x; d3 = (int)db.y;
    } else {
        int4 sv = ((const int4*)src)[i];
        int4 dv = ((const int4*)dst)[i];
        s0 = sv.x; s1 = sv.y; s2 = sv.z; s3 = sv.w;
        d0 = dv.x; d1 = dv.y; d2 = dv.z; d3 = dv.w;
    }
    int p0 = atomicAdd(&g_count[d0], 1);
    int p1 = atomicAdd(&g_count[d1], 1);
    int p2 = atomicAdd(&g_count[d2], 1);
    int p3 = atomicAdd(&g_count[d3], 1);
    if (p0 < CAP_) g_bucket[d0 * CAP_ + p0] = s0;
    if (p1 < CAP_) g_bucket[d1 * CAP_ + p1] = s1;
    if (p2 < CAP_) g_bucket[d2 * CAP_ + p2] = s2;
    if (p3 < CAP_) g_bucket[d3 * CAP_ + p3] = s3;
}

// ===========================================================================
// Kernel 2: HMMA fp16 GEMM  m = H @ W  -> g_mh (fp16, node-interleaved).
// CTA tile 128x128 (K=128), 8 warps, warp tile 64x32.
// A: As[row][k] row-major; B: Wk[k][n] row-major (coalesced staging, NO
// scalar LDGs). Fragments via ldmatrix.x4 (A) / ldmatrix.x2.trans (B).
// Epilogue staged through smem for coalesced uint4 global stores.
// ===========================================================================
#define ASTR   136                   // halves per As/Cs/Wk row (272B)
#define SM_TILE_HALVES (128 * ASTR)  // 17408
#define SM_TOT_BYTES (2 * SM_TILE_HALVES * 2)   // 69632

__device__ __forceinline__ void mma16816(float* c, const uint32_t* a,
                                         const uint32_t* b) {
    asm volatile(
        "mma.sync.aligned.m16n8k16.row.col.f32.f16.f16.f32 "
        "{%0,%1,%2,%3}, {%4,%5,%6,%7}, {%8,%9}, {%0,%1,%2,%3};"
        : "+f"(c[0]), "+f"(c[1]), "+f"(c[2]), "+f"(c[3])
        : "r"(a[0]), "r"(a[1]), "r"(a[2]), "r"(a[3]), "r"(b[0]), "r"(b[1]));
}
#define LDSM_X4(r0, r1, r2, r3, addr)                                        \
    asm volatile("ldmatrix.sync.aligned.m8n8.x4.shared.b16 {%0,%1,%2,%3}, [%4];" \
                 : "=r"(r0), "=r"(r1), "=r"(r2), "=r"(r3) : "r"(addr))
#define LDSM_X2_T(r0, r1, addr)                                              \
    asm volatile("ldmatrix.sync.aligned.m8n8.x2.trans.shared.b16 {%0,%1}, [%2];" \
                 : "=r"(r0), "=r"(r1) : "r"(addr))

__global__ __launch_bounds__(256)
void gemm_hmma_kernel(const float* __restrict__ Hm, const float* __restrict__ W) {
    extern __shared__ __half sm[];
    __half* As = sm;                    // [128][ASTR] (row, k); reused as Cs
    __half* Wk = sm + SM_TILE_HALVES;   // [128][ASTR] (k, n) row-major

    const int tid  = threadIdx.x;
    const int wid  = tid >> 5;
    const int lane = tid & 31;
    const int gid  = lane >> 2;      // 0..7
    const int tg   = lane & 3;       // 0..3
    const int row0 = blockIdx.x * 128;

    const uint32_t smem_u32 =
        (uint32_t)__cvta_generic_to_shared(sm);
    const uint32_t As_u32 = smem_u32;
    const uint32_t Wk_u32 = smem_u32 + SM_TILE_HALVES * 2;

    // Stage A: 4096 float4 reads, fp32 -> fp16 (coalesced)
#pragma unroll
    for (int it = 0; it < 16; it++) {
        int idx4 = it * 256 + tid;          // 0..4095
        int r = idx4 >> 5;
        int c = (idx4 & 31) * 4;
        int gr = row0 + r;
        float4 v = make_float4(0.f, 0.f, 0.f, 0.f);
        if (gr < ROWS_) v = *(const float4*)&Hm[(size_t)gr * D_ + c];
        __half2 h01 = __float22half2_rn(make_float2(v.x, v.y));
        __half2 h23 = __float22half2_rn(make_float2(v.z, v.w));
        unsigned long long packed =
            (unsigned long long)(*(uint32_t*)&h01) |
            ((unsigned long long)(*(uint32_t*)&h23) << 32);
        *(unsigned long long*)&As[r * ASTR + c] = packed;
    }
    // Stage B: Wk[k][n] row-major, coalesced float4 reads, 8B vector stores.
#pragma unroll
    for (int it = 0; it < 16; it++) {
        int idx4 = it * 256 + tid;          // 0..4095
        int k = idx4 >> 5;
        int n = (idx4 & 31) * 4;
        float4 v = *(const float4*)&W[k * 128 + n];
        __half2 h01 = __float22half2_rn(make_float2(v.x, v.y));
        __half2 h23 = __float22half2_rn(make_float2(v.z, v.w));
        unsigned long long packed =
            (unsigned long long)(*(uint32_t*)&h01) |
            ((unsigned long long)(*(uint32_t*)&h23) << 32);
        *(unsigned long long*)&Wk[k * ASTR + n] = packed;
    }
    __syncthreads();

    const int wr = wid >> 2;         // 0..1 : row block of 64
    const int wc = wid & 3;          // 0..3 : col block of 32

    // ldmatrix lane address bases (byte offsets into shared space)
    // A (x4): lane l -> row r0m + (l&7) + ((l>>3)&1)*8, col (l>>4)*8
    const int a_lr = (lane & 7) + ((lane >> 3) & 1) * 8;
    const int a_lk = (lane >> 4) * 8;
    uint32_t a_base[4];
#pragma unroll
    for (int mt = 0; mt < 4; mt++) {
        int r = wr * 64 + mt * 16 + a_lr;
        a_base[mt] = As_u32 + (uint32_t)((r * ASTR + a_lk) * 2);
    }
    // B (x2.trans): lane l (0..15) -> k-row k0 + (l&15), col n0
    const int b_lk = lane & 15;
    uint32_t b_base[4];
#pragma unroll
    for (int nt = 0; nt < 4; nt++) {
        int n = wc * 32 + nt * 8;
        b_base[nt] = Wk_u32 + (uint32_t)((b_lk * ASTR + n) * 2);
    }

    float acc[16][4];
#pragma unroll
    for (int i = 0; i < 16; i++)
#pragma unroll
        for (int j = 0; j < 4; j++) acc[i][j] = 0.f;

#pragma unroll
    for (int ks = 0; ks < 8; ks++) {
        const uint32_t aoff = (uint32_t)(ks * 16 * 2);          // k0*2 bytes
        const uint32_t boff = (uint32_t)(ks * 16 * ASTR * 2);   // k0 rows
        uint32_t af[4][4], bf[4][2];
#pragma unroll
        for (int mt = 0; mt < 4; mt++)
            LDSM_X4(af[mt][0], af[mt][1], af[mt][2], af[mt][3],
                    a_base[mt] + aoff);
#pragma unroll
        for (int nt = 0; nt < 4; nt++)
            LDSM_X2_T(bf[nt][0], bf[nt][1], b_base[nt] + boff);
#pragma unroll
        for (int mt = 0; mt < 4; mt++)
#pragma unroll
            for (int nt = 0; nt < 4; nt++)
                mma16816(acc[mt * 4 + nt], af[mt], bf[nt]);
    }

    // Epilogue: fragments -> Cs (reuse As; conflict-free), coalesced writeout.
    __syncthreads();
    __half* Cs = As;
#pragma unroll
    for (int mt = 0; mt < 4; mt++) {
#pragma unroll
        for (int hf = 0; hf < 2; hf++) {
            int r = wr * 64 + mt * 16 + gid + hf * 8;
#pragma unroll
            for (int nt = 0; nt < 4; nt++) {
                float* c = acc[mt * 4 + nt];
                float2 f = hf ? make_float2(c[2], c[3])
                              : make_float2(c[0], c[1]);
                __half2 h = __float22half2_rn(f);
                *(__half2*)&Cs[r * ASTR + wc * 32 + nt * 8 + tg * 2] = h;
            }
        }
    }
    __syncthreads();
    // 2048 uint4 (8 halves each): 256 threads x 8 iterations, coalesced.
#pragma unroll
    for (int it = 0; it < 8; it++) {
        int idx = it * 256 + tid;     // 0..2047
        int r = idx >> 4;             // 16 uint4 per row
        int c = (idx & 15) * 8;
        int gr = row0 + r;
        if (gr < ROWS_) {
            int b = (gr >= N_) ? 1 : 0;
            int n = gr - b * N_;
            *(uint4*)(g_mh + (size_t)n * 256 + b * 128 + c) =
                *(uint4*)&Cs[r * ASTR + c];
        }
    }
}

// ===========================================================================
// Kernel 3: fused gather + gelu + residual + LayerNorm.
// Edge-paired inner loop: hadd2 two edges in fp16, one fp32 accumulate/pair.
// ===========================================================================
__device__ __forceinline__ float gelu_exact(float v) {
    return 0.5f * v * (1.0f + erff(v * 0.70710678118654752f));
}
__device__ __forceinline__ float half_sum(float s) {
#pragma unroll
    for (int o = 8; o > 0; o >>= 1) s += __shfl_xor_sync(0xffffffffu, s, o);
    return s;
}

__global__ __launch_bounds__(256)
void gather_ln_kernel(const float* __restrict__ Hm,
                      const float* __restrict__ gamma,
                      const float* __restrict__ beta,
                      float* __restrict__ out) {
    const int node = (blockIdx.x * blockDim.x + threadIdx.x) >> 5;
    const int lane = threadIdx.x & 31;
    if (node >= N_) return;

    int deg = g_count[node];
    if (deg > CAP_) deg = CAP_;

    const int bsel = lane >> 4;
    const int fg   = lane & 15;
    const size_t rowoff = (size_t)(bsel * N_ + node) * D_ + fg * 8;
    float4 h0 = *(const float4*)(Hm + rowoff);
    float4 h1 = *(const float4*)(Hm + rowoff + 4);

    const int* bucket = g_bucket + (size_t)node * CAP_;
    int id0 = (lane      < deg) ? bucket[lane]      : 0;
    int id1 = (lane + 32 < deg) ? bucket[lane + 32] : 0;

    if (lane == 0) g_count[node] = 0;  // reset for next replay

    const size_t laneoff = (size_t)lane * 8;
    float a0 = 0.f, a1 = 0.f, a2 = 0.f, a3 = 0.f;
    float a4 = 0.f, a5 = 0.f, a6 = 0.f, a7 = 0.f;

#define ACC_PAIRSUM(p0, p1, p2, p3)                         \
    do {                                                    \
        float2 f0 = __half22float2(p0);                     \
        float2 f1 = __half22float2(p1);                     \
        float2 f2 = __half22float2(p2);                     \
        float2 f3 = __half22float2(p3);                     \
        a0 += f0.x; a1 += f0.y; a2 += f1.x; a3 += f1.y;     \
        a4 += f2.x; a5 += f2.y; a6 += f3.x; a7 += f3.y;     \
    } while (0)

#define ACC_SINGLE(v)                                       \
    ACC_PAIRSUM(*(__half2*)&(v).x, *(__half2*)&(v).y,       \
                *(__half2*)&(v).z, *(__half2*)&(v).w)

    int c0 = min(deg, 32);
    int j = 0;
#pragma unroll 2
    for (; j + 2 <= c0; j += 2) {
        int s0 = __shfl_sync(0xffffffffu, id0, j);
        int s1 = __shfl_sync(0xffffffffu, id0, j + 1);
        uint4 v0 = *(const uint4*)(g_mh + (size_t)s0 * 256 + laneoff);
        uint4 v1 = *(const uint4*)(g_mh + (size_t)s1 * 256 + laneoff);
        __half2 p0 = __hadd2(*(__half2*)&v0.x, *(__half2*)&v1.x);
        __half2 p1 = __hadd2(*(__half2*)&v0.y, *(__half2*)&v1.y);
        __half2 p2 = __hadd2(*(__half2*)&v0.z, *(__half2*)&v1.z);
        __half2 p3 = __hadd2(*(__half2*)&v0.w, *(__half2*)&v1.w);
        ACC_PAIRSUM(p0, p1, p2, p3);
    }
    if (j < c0) {
        int s = __shfl_sync(0xffffffffu, id0, j);
        uint4 v = *(const uint4*)(g_mh + (size_t)s * 256 + laneoff);
        ACC_SINGLE(v);
    }
    int c1 = deg - 32;
    j = 0;
#pragma unroll 2
    for (; j + 2 <= c1; j += 2) {
        int s0 = __shfl_sync(0xffffffffu, id1, j);
        int s1 = __shfl_sync(0xffffffffu, id1, j + 1);
        uint4 v0 = *(const uint4*)(g_mh + (size_t)s0 * 256 + laneoff);
        uint4 v1 = *(const uint4*)(g_mh + (size_t)s1 * 256 + laneoff);
        __half2 p0 = __hadd2(*(__half2*)&v0.x, *(__half2*)&v1.x);
        __half2 p1 = __hadd2(*(__half2*)&v0.y, *(__half2*)&v1.y);
        __half2 p2 = __hadd2(*(__half2*)&v0.z, *(__half2*)&v1.z);
        __half2 p3 = __hadd2(*(__half2*)&v0.w, *(__half2*)&v1.w);
        ACC_PAIRSUM(p0, p1, p2, p3);
    }
    if (j >= 0 && j < c1) {
        int s = __shfl_sync(0xffffffffu, id1, j);
        uint4 v = *(const uint4*)(g_mh + (size_t)s * 256 + laneoff);
        ACC_SINGLE(v);
    }

    float x0 = h0.x + gelu_exact(a0);
    float x1 = h0.y + gelu_exact(a1);
    float x2 = h0.z + gelu_exact(a2);
    float x3 = h0.w + gelu_exact(a3);
    float x4 = h1.x + gelu_exact(a4);
    float x5 = h1.y + gelu_exact(a5);
    float x6 = h1.z + gelu_exact(a6);
    float x7 = h1.w + gelu_exact(a7);

    float mean = half_sum(x0 + x1 + x2 + x3 + x4 + x5 + x6 + x7) * (1.0f / D_);

    float d0 = x0 - mean, d1 = x1 - mean, d2 = x2 - mean, d3 = x3 - mean;
    float d4 = x4 - mean, d5 = x5 - mean, d6 = x6 - mean, d7 = x7 - mean;
    float var = half_sum(d0 * d0 + d1 * d1 + d2 * d2 + d3 * d3 +
                         d4 * d4 + d5 * d5 + d6 * d6 + d7 * d7) * (1.0f / D_);
    float inv = rsqrtf(var + 1e-5f);

    float4 g0 = *(const float4*)(gamma + fg * 8);
    float4 g1 = *(const float4*)(gamma + fg * 8 + 4);
    float4 b0 = *(const float4*)(beta + fg * 8);
    float4 b1 = *(const float4*)(beta + fg * 8 + 4);

    float4 o0, o1;
    o0.x = d0 * inv * g0.x + b0.x;
    o0.y = d1 * inv * g0.y + b0.y;
    o0.z = d2 * inv * g0.z + b0.z;
    o0.w = d3 * inv * g0.w + b0.w;
    o1.x = d4 * inv * g1.x + b1.x;
    o1.y = d5 * inv * g1.y + b1.y;
    o1.z = d6 * inv * g1.z + b1.z;
    o1.w = d7 * inv * g1.w + b1.w;
    *(float4*)(out + rowoff)     = o0;
    *(float4*)(out + rowoff + 4) = o1;
}

// ===========================================================================
// Launcher: fork HMMA-GEMM onto side stream; probe+fill on main; join; gather.
// ===========================================================================
extern "C" void kernel_launch(void* const* d_in, const int* in_sizes, int n_in,
                              void* d_out, int out_size) {
    const float* H     = (const float*)d_in[0];
    const void*  src   = d_in[1];
    const void*  dst   = d_in[2];
    const float* W     = (const float*)d_in[3];
    const float* gamma = (const float*)d_in[4];
    const float* beta  = (const float*)d_in[5];
    float*       out   = (float*)d_out;

    (void)in_sizes; (void)n_in; (void)out_size;

    cudaFuncSetAttribute(gemm_hmma_kernel,
                         cudaFuncAttributeMaxDynamicSharedMemorySize,
                         SM_TOT_BYTES);

    cudaStream_t side;
    cudaStreamCreateWithFlags(&side, cudaStreamNonBlocking);
    cudaEvent_t eFork, eJoin;
    cudaEventCreateWithFlags(&eFork, cudaEventDisableTiming);
    cudaEventCreateWithFlags(&eJoin, cudaEventDisableTiming);

    // fork: GEMM does not depend on the index probe
    cudaEventRecord(eFork, 0);
    cudaStreamWaitEvent(side, eFork, 0);
    gemm_hmma_kernel<<<(ROWS_ + 127) / 128, 256, SM_TOT_BYTES, side>>>(H, W);
    cudaEventRecord(eJoin, side);

    // main stream: probe -> bucket fill
    detect_idx_kernel<<<1, 32>>>((const unsigned int*)src,
                                 (const unsigned int*)dst);
    fill_kernel<<<(E_ / 4 + 255) / 256, 256>>>(src, dst);

    // join: gather needs buckets + GEMM output
    cudaStreamWaitEvent(0, eJoin, 0);
    gather_ln_kernel<<<(N_ * 32 + 255) / 256, 256>>>(H, gamma, beta, out);
}

// round 15
// speedup vs baseline: 3.1243x; 1.0983x over previous
#include <cuda_runtime.h>
#include <cuda_fp16.h>
#include <math.h>
#include <cstdint>

// Problem shape (fixed by dataset)
#define B_    2
#define N_    50000
#define D_    128
#define E_    800000
#define ROWS_ (B_ * N_)   // 100000 rows when H viewed as [B*N, D]
#define CAP_  64          // per-node bucket capacity (P(deg>=64) ~ 2e-18/node)

// Scratch: device globals (no allocation allowed)
// m stored fp16, node-interleaved: g_mh[node*256 + batch*128 + d]
__device__ __half g_mh[(size_t)N_ * 256];
__device__ int    g_count[N_];                 // degree/cursor; re-zeroed by gather
__device__ int    g_bucket[(size_t)N_ * CAP_]; // edge src ids bucketed by dst

// ===========================================================================
// Hybrid kernel: even blocks = HMMA GEMM tile, odd blocks = bucket fill.
// 782 GEMM blocks + 782 fill blocks, interleaved for immediate overlap.
// ===========================================================================
#define ASTR   136                   // halves per As/Cs/Wk row (272B)
#define SM_TILE_HALVES (128 * ASTR)  // 17408
#define SM_TOT_BYTES (2 * SM_TILE_HALVES * 2)   // 69632
#define GEMM_BLOCKS 782
#define FILL_BLOCKS 782              // 800000 / 4 / 256 = 781.25 -> 782

__device__ __forceinline__ void mma16816(float* c, const uint32_t* a,
                                         const uint32_t* b) {
    asm volatile(
        "mma.sync.aligned.m16n8k16.row.col.f32.f16.f16.f32 "
        "{%0,%1,%2,%3}, {%4,%5,%6,%7}, {%8,%9}, {%0,%1,%2,%3};"
        : "+f"(c[0]), "+f"(c[1]), "+f"(c[2]), "+f"(c[3])
        : "r"(a[0]), "r"(a[1]), "r"(a[2]), "r"(a[3]), "r"(b[0]), "r"(b[1]));
}
#define LDSM_X4(r0, r1, r2, r3, addr)                                        \
    asm volatile("ldmatrix.sync.aligned.m8n8.x4.shared.b16 {%0,%1,%2,%3}, [%4];" \
                 : "=r"(r0), "=r"(r1), "=r"(r2), "=r"(r3) : "r"(addr))
#define LDSM_X2_T(r0, r1, addr)                                              \
    asm volatile("ldmatrix.sync.aligned.m8n8.x2.trans.shared.b16 {%0,%1}, [%2];" \
                 : "=r"(r0), "=r"(r1) : "r"(addr))

__device__ __forceinline__ void gemm_block(int tileid, const float* __restrict__ Hm,
                                           const float* __restrict__ W,
                                           __half* sm) {
    __half* As = sm;                    // [128][ASTR] (row, k); reused as Cs
    __half* Wk = sm + SM_TILE_HALVES;   // [128][ASTR] (k, n) row-major

    const int tid  = threadIdx.x;
    const int wid  = tid >> 5;
    const int lane = tid & 31;
    const int gid  = lane >> 2;      // 0..7
    const int tg   = lane & 3;       // 0..3
    const int row0 = tileid * 128;

    const uint32_t smem_u32 = (uint32_t)__cvta_generic_to_shared(sm);
    const uint32_t As_u32 = smem_u32;
    const uint32_t Wk_u32 = smem_u32 + SM_TILE_HALVES * 2;

    // Stage A: 4096 float4 reads, fp32 -> fp16 (coalesced)
#pragma unroll
    for (int it = 0; it < 16; it++) {
        int idx4 = it * 256 + tid;          // 0..4095
        int r = idx4 >> 5;
        int c = (idx4 & 31) * 4;
        int gr = row0 + r;
        float4 v = make_float4(0.f, 0.f, 0.f, 0.f);
        if (gr < ROWS_) v = *(const float4*)&Hm[(size_t)gr * D_ + c];
        __half2 h01 = __float22half2_rn(make_float2(v.x, v.y));
        __half2 h23 = __float22half2_rn(make_float2(v.z, v.w));
        unsigned long long packed =
            (unsigned long long)(*(uint32_t*)&h01) |
            ((unsigned long long)(*(uint32_t*)&h23) << 32);
        *(unsigned long long*)&As[r * ASTR + c] = packed;
    }
    // Stage B: Wk[k][n] row-major, coalesced float4 reads, 8B vector stores.
#pragma unroll
    for (int it = 0; it < 16; it++) {
        int idx4 = it * 256 + tid;          // 0..4095
        int k = idx4 >> 5;
        int n = (idx4 & 31) * 4;
        float4 v = *(const float4*)&W[k * 128 + n];
        __half2 h01 = __float22half2_rn(make_float2(v.x, v.y));
        __half2 h23 = __float22half2_rn(make_float2(v.z, v.w));
        unsigned long long packed =
            (unsigned long long)(*(uint32_t*)&h01) |
            ((unsigned long long)(*(uint32_t*)&h23) << 32);
        *(unsigned long long*)&Wk[k * ASTR + n] = packed;
    }
    __syncthreads();

    const int wr = wid >> 2;         // 0..1 : row block of 64
    const int wc = wid & 3;          // 0..3 : col block of 32

    const int a_lr = (lane & 7) + ((lane >> 3) & 1) * 8;
    const int a_lk = (lane >> 4) * 8;
    uint32_t a_base[4];
#pragma unroll
    for (int mt = 0; mt < 4; mt++) {
        int r = wr * 64 + mt * 16 + a_lr;
        a_base[mt] = As_u32 + (uint32_t)((r * ASTR + a_lk) * 2);
    }
    const int b_lk = lane & 15;
    uint32_t b_base[4];
#pragma unroll
    for (int nt = 0; nt < 4; nt++) {
        int n = wc * 32 + nt * 8;
        b_base[nt] = Wk_u32 + (uint32_t)((b_lk * ASTR + n) * 2);
    }

    float acc[16][4];
#pragma unroll
    for (int i = 0; i < 16; i++)
#pragma unroll
        for (int j = 0; j < 4; j++) acc[i][j] = 0.f;

#pragma unroll
    for (int ks = 0; ks < 8; ks++) {
        const uint32_t aoff = (uint32_t)(ks * 16 * 2);
        const uint32_t boff = (uint32_t)(ks * 16 * ASTR * 2);
        uint32_t af[4][4], bf[4][2];
#pragma unroll
        for (int mt = 0; mt < 4; mt++)
            LDSM_X4(af[mt][0], af[mt][1], af[mt][2], af[mt][3],
                    a_base[mt] + aoff);
#pragma unroll
        for (int nt = 0; nt < 4; nt++)
            LDSM_X2_T(bf[nt][0], bf[nt][1], b_base[nt] + boff);
#pragma unroll
        for (int mt = 0; mt < 4; mt++)
#pragma unroll
            for (int nt = 0; nt < 4; nt++)
                mma16816(acc[mt * 4 + nt], af[mt], bf[nt]);
    }

    // Epilogue: fragments -> Cs (reuse As; conflict-free), coalesced writeout.
    __syncthreads();
    __half* Cs = As;
#pragma unroll
    for (int mt = 0; mt < 4; mt++) {
#pragma unroll
        for (int hf = 0; hf < 2; hf++) {
            int r = wr * 64 + mt * 16 + gid + hf * 8;
#pragma unroll
            for (int nt = 0; nt < 4; nt++) {
                float* c = acc[mt * 4 + nt];
                float2 f = hf ? make_float2(c[2], c[3])
                              : make_float2(c[0], c[1]);
                __half2 h = __float22half2_rn(f);
                *(__half2*)&Cs[r * ASTR + wc * 32 + nt * 8 + tg * 2] = h;
            }
        }
    }
    __syncthreads();
#pragma unroll
    for (int it = 0; it < 8; it++) {
        int idx = it * 256 + tid;     // 0..2047
        int r = idx >> 4;             // 16 uint4 per row
        int c = (idx & 15) * 8;
        int gr = row0 + r;
        if (gr < ROWS_) {
            int b = (gr >= N_) ? 1 : 0;
            int n = gr - b * N_;
            *(uint4*)(g_mh + (size_t)n * 256 + b * 128 + c) =
                *(uint4*)&Cs[r * ASTR + c];
        }
    }
}

__device__ __forceinline__ void fill_block(int fillid,
                                           const void* __restrict__ src,
                                           const void* __restrict__ dst,
                                           __half* sm) {
    const int tid = threadIdx.x;

    // Inline index-dtype probe (per block, deterministic):
    // int64 indices < 50000 have zero odd 32-bit words. 128 genuine random
    // int32 indices all being zero has probability ~(1/50000)^128.
    __shared__ int any_nonzero;
    if (tid == 0) any_nonzero = 0;
    __syncthreads();
    if (tid < 64) {
        unsigned int w = ((const unsigned int*)src)[2 * tid + 1] |
                         ((const unsigned int*)dst)[2 * tid + 1];
        if (w) atomicOr(&any_nonzero, 1);
    }
    __syncthreads();
    const int is64 = (any_nonzero == 0);

    int i = fillid * 256 + tid;          // 4 edges per thread
    if (i * 4 >= E_) return;
    int s0, s1, s2, s3, d0, d1, d2, d3;
    if (is64) {
        longlong2 sa = ((const longlong2*)src)[i * 2];
        longlong2 sb = ((const longlong2*)src)[i * 2 + 1];
        longlong2 da = ((const longlong2*)dst)[i * 2];
        longlong2 db = ((const longlong2*)dst)[i * 2 + 1];
        s0 = (int)sa.x; s1 = (int)sa.y; s2 = (int)sb.x; s3 = (int)sb.y;
        d0 = (int)da.x; d1 = (int)da.y; d2 = (int)db.x; d3 = (int)db.y;
    } else {
        int4 sv = ((const int4*)src)[i];
        int4 dv = ((const int4*)dst)[i];
        s0 = sv.x; s1 = sv.y; s2 = sv.z; s3 = sv.w;
        d0 = dv.x; d1 = dv.y; d2 = dv.z; d3 = dv.w;
    }
    int p0 = atomicAdd(&g_count[d0], 1);
    int p1 = atomicAdd(&g_count[d1], 1);
    int p2 = atomicAdd(&g_count[d2], 1);
    int p3 = atomicAdd(&g_count[d3], 1);
    if (p0 < CAP_) g_bucket[d0 * CAP_ + p0] = s0;
    if (p1 < CAP_) g_bucket[d1 * CAP_ + p1] = s1;
    if (p2 < CAP_) g_bucket[d2 * CAP_ + p2] = s2;
    if (p3 < CAP_) g_bucket[d3 * CAP_ + p3] = s3;
}

__global__ __launch_bounds__(256)
void hybrid_kernel(const float* __restrict__ Hm, const float* __restrict__ W,
                   const void* __restrict__ src, const void* __restrict__ dst) {
    extern __shared__ __half sm[];
    const int bid = blockIdx.x;
    if ((bid & 1) == 0) {
        int tileid = bid >> 1;
        if (tileid < GEMM_BLOCKS) gemm_block(tileid, Hm, W, sm);
    } else {
        int fillid = bid >> 1;
        if (fillid < FILL_BLOCKS) fill_block(fillid, src, dst, sm);
    }
}

// ===========================================================================
// Gather kernel: fused gather + gelu + residual + LayerNorm (unchanged).
// ===========================================================================
__device__ __forceinline__ float gelu_exact(float v) {
    return 0.5f * v * (1.0f + erff(v * 0.70710678118654752f));
}
__device__ __forceinline__ float half_sum(float s) {
#pragma unroll
    for (int o = 8; o > 0; o >>= 1) s += __shfl_xor_sync(0xffffffffu, s, o);
    return s;
}

__global__ __launch_bounds__(256)
void gather_ln_kernel(const float* __restrict__ Hm,
                      const float* __restrict__ gamma,
                      const float* __restrict__ beta,
                      float* __restrict__ out) {
    const int node = (blockIdx.x * blockDim.x + threadIdx.x) >> 5;
    const int lane = threadIdx.x & 31;
    if (node >= N_) return;

    int deg = g_count[node];
    if (deg > CAP_) deg = CAP_;

    const int bsel = lane >> 4;
    const int fg   = lane & 15;
    const size_t rowoff = (size_t)(bsel * N_ + node) * D_ + fg * 8;
    float4 h0 = *(const float4*)(Hm + rowoff);
    float4 h1 = *(const float4*)(Hm + rowoff + 4);

    const int* bucket = g_bucket + (size_t)node * CAP_;
    int id0 = (lane      < deg) ? bucket[lane]      : 0;
    int id1 = (lane + 32 < deg) ? bucket[lane + 32] : 0;

    if (lane == 0) g_count[node] = 0;  // reset for next replay

    const size_t laneoff = (size_t)lane * 8;
    float a0 = 0.f, a1 = 0.f, a2 = 0.f, a3 = 0.f;
    float a4 = 0.f, a5 = 0.f, a6 = 0.f, a7 = 0.f;

#define ACC_PAIRSUM(p0, p1, p2, p3)                         \
    do {                                                    \
        float2 f0 = __half22float2(p0);                     \
        float2 f1 = __half22float2(p1);                     \
        float2 f2 = __half22float2(p2);                     \
        float2 f3 = __half22float2(p3);                     \
        a0 += f0.x; a1 += f0.y; a2 += f1.x; a3 += f1.y;     \
        a4 += f2.x; a5 += f2.y; a6 += f3.x; a7 += f3.y;     \
    } while (0)

#define ACC_SINGLE(v)                                       \
    ACC_PAIRSUM(*(__half2*)&(v).x, *(__half2*)&(v).y,       \
                *(__half2*)&(v).z, *(__half2*)&(v).w)

    int c0 = min(deg, 32);
    int j = 0;
#pragma unroll 2
    for (; j + 2 <= c0; j += 2) {
        int s0 = __shfl_sync(0xffffffffu, id0, j);
        int s1 = __shfl_sync(0xffffffffu, id0, j + 1);
        uint4 v0 = *(const uint4*)(g_mh + (size_t)s0 * 256 + laneoff);
        uint4 v1 = *(const uint4*)(g_mh + (size_t)s1 * 256 + laneoff);
        __half2 p0 = __hadd2(*(__half2*)&v0.x, *(__half2*)&v1.x);
        __half2 p1 = __hadd2(*(__half2*)&v0.y, *(__half2*)&v1.y);
        __half2 p2 = __hadd2(*(__half2*)&v0.z, *(__half2*)&v1.z);
        __half2 p3 = __hadd2(*(__half2*)&v0.w, *(__half2*)&v1.w);
        ACC_PAIRSUM(p0, p1, p2, p3);
    }
    if (j < c0) {
        int s = __shfl_sync(0xffffffffu, id0, j);
        uint4 v = *(const uint4*)(g_mh + (size_t)s * 256 + laneoff);
        ACC_SINGLE(v);
    }
    int c1 = deg - 32;
    j = 0;
#pragma unroll 2
    for (; j + 2 <= c1; j += 2) {
        int s0 = __shfl_sync(0xffffffffu, id1, j);
        int s1 = __shfl_sync(0xffffffffu, id1, j + 1);
        uint4 v0 = *(const uint4*)(g_mh + (size_t)s0 * 256 + laneoff);
        uint4 v1 = *(const uint4*)(g_mh + (size_t)s1 * 256 + laneoff);
        __half2 p0 = __hadd2(*(__half2*)&v0.x, *(__half2*)&v1.x);
        __half2 p1 = __hadd2(*(__half2*)&v0.y, *(__half2*)&v1.y);
        __half2 p2 = __hadd2(*(__half2*)&v0.z, *(__half2*)&v1.z);
        __half2 p3 = __hadd2(*(__half2*)&v0.w, *(__half2*)&v1.w);
        ACC_PAIRSUM(p0, p1, p2, p3);
    }
    if (j >= 0 && j < c1) {
        int s = __shfl_sync(0xffffffffu, id1, j);
        uint4 v = *(const uint4*)(g_mh + (size_t)s * 256 + laneoff);
        ACC_SINGLE(v);
    }

    float x0 = h0.x + gelu_exact(a0);
    float x1 = h0.y + gelu_exact(a1);
    float x2 = h0.z + gelu_exact(a2);
    float x3 = h0.w + gelu_exact(a3);
    float x4 = h1.x + gelu_exact(a4);
    float x5 = h1.y + gelu_exact(a5);
    float x6 = h1.z + gelu_exact(a6);
    float x7 = h1.w + gelu_exact(a7);

    float mean = half_sum(x0 + x1 + x2 + x3 + x4 + x5 + x6 + x7) * (1.0f / D_);

    float d0 = x0 - mean, d1 = x1 - mean, d2 = x2 - mean, d3 = x3 - mean;
    float d4 = x4 - mean, d5 = x5 - mean, d6 = x6 - mean, d7 = x7 - mean;
    float var = half_sum(d0 * d0 + d1 * d1 + d2 * d2 + d3 * d3 +
                         d4 * d4 + d5 * d5 + d6 * d6 + d7 * d7) * (1.0f / D_);
    float inv = rsqrtf(var + 1e-5f);

    float4 g0 = *(const float4*)(gamma + fg * 8);
    float4 g1 = *(const float4*)(gamma + fg * 8 + 4);
    float4 b0 = *(const float4*)(beta + fg * 8);
    float4 b1 = *(const float4*)(beta + fg * 8 + 4);

    float4 o0, o1;
    o0.x = d0 * inv * g0.x + b0.x;
    o0.y = d1 * inv * g0.y + b0.y;
    o0.z = d2 * inv * g0.z + b0.z;
    o0.w = d3 * inv * g0.w + b0.w;
    o1.x = d4 * inv * g1.x + b1.x;
    o1.y = d5 * inv * g1.y + b1.y;
    o1.z = d6 * inv * g1.z + b1.z;
    o1.w = d7 * inv * g1.w + b1.w;
    *(float4*)(out + rowoff)     = o0;
    *(float4*)(out + rowoff + 4) = o1;
}

// ===========================================================================
// Launcher: 2 kernels, single stream, no events.
// ===========================================================================
extern "C" void kernel_launch(void* const* d_in, const int* in_sizes, int n_in,
                              void* d_out, int out_size) {
    const float* H     = (const float*)d_in[0];
    const void*  src   = d_in[1];
    const void*  dst   = d_in[2];
    const float* W     = (const float*)d_in[3];
    const float* gamma = (const float*)d_in[4];
    const float* beta  = (const float*)d_in[5];
    float*       out   = (float*)d_out;

    (void)in_sizes; (void)n_in; (void)out_size;

    cudaFuncSetAttribute(hybrid_kernel,
                         cudaFuncAttributeMaxDynamicSharedMemorySize,
                         SM_TOT_BYTES);

    // Phase 1: GEMM (even blocks) + probe&fill (odd blocks), one kernel.
    hybrid_kernel<<<2 * GEMM_BLOCKS, 256, SM_TOT_BYTES>>>(H, W, src, dst);
    // Phase 2: fused gather + gelu + residual + LayerNorm.
    gather_ln_kernel<<<(N_ * 32 + 255) / 256, 256>>>(H, gamma, beta, out);
}